// round 2
// baseline (speedup 1.0000x reference)
#include <cuda_runtime.h>
#include <cuda_bf16.h>
#include <math.h>

// ---------------- problem constants ----------------
#define Dd 6
#define Hh 128
#define Ww 128
#define Cc 180
#define NHh 6
#define HDd 30
#define Nn 128            // tokens per window
#define NWIN 768          // (6/2)*(128/8)*(128/8)
#define NTOK (NWIN * Nn)  // 98304
#define HIDd 360
#define SCALEF 0.18257418583505536f  // 30^-0.5

// ---------------- scratch (device globals; no allocs) ----------------
__device__ float g_xw  [NTOK * Cc];        // windowed LN1 output
__device__ float g_qkvs[NTOK * 3 * Cc];    // self qkv
__device__ float g_qkvm[NTOK * 3 * Cc];    // mutual qkv
__device__ float g_xo  [NTOK * 2 * Cc];    // concat(mut, self)
__device__ float g_proj[NTOK * Cc];
__device__ float g_y   [NTOK * Cc];        // x + attn branch (natural layout)
__device__ float g_h2  [NTOK * Cc];        // LN2
__device__ float g_a1  [NTOK * HIDd];
__device__ float g_a2  [NTOK * HIDd];
__device__ float g_hid [NTOK * HIDd];

// ---------------- LN1 + roll + window partition ----------------
__global__ void ln1_window_k(const float* __restrict__ x,
                             const float* __restrict__ g,
                             const float* __restrict__ b,
                             float* __restrict__ xw)
{
    int warp = (blockIdx.x * blockDim.x + threadIdx.x) >> 5;
    int lane = threadIdx.x & 31;
    if (warp >= NTOK) return;
    // warp indexes rolled coordinate (dp,hp,wp)
    int dp = warp / (Hh * Ww);
    int rem = warp % (Hh * Ww);
    int hp = rem >> 7;
    int wp = rem & 127;
    int sd = dp + 1; if (sd >= Dd) sd -= Dd;
    int sh = (hp + 4) & 127;
    int sw = (wp + 4) & 127;
    const float* src = x + ((size_t)(sd * Hh + sh) * Ww + sw) * Cc;

    float vals[6];
    float sum = 0.f, sq = 0.f;
#pragma unroll
    for (int i = 0; i < 6; i++) {
        int c = lane + i * 32;
        float v = (c < Cc) ? src[c] : 0.f;
        vals[i] = v; sum += v; sq += v * v;
    }
#pragma unroll
    for (int o = 16; o; o >>= 1) {
        sum += __shfl_xor_sync(0xffffffffu, sum, o);
        sq  += __shfl_xor_sync(0xffffffffu, sq, o);
    }
    float mean = sum * (1.f / Cc);
    float var  = sq * (1.f / Cc) - mean * mean;
    float rstd = rsqrtf(var + 1e-5f);

    int win = (dp >> 1) * 256 + (hp >> 3) * 16 + (wp >> 3);
    int tok = (dp & 1) * 64 + (hp & 7) * 8 + (wp & 7);
    float* dst = xw + (size_t)(win * Nn + tok) * Cc;
#pragma unroll
    for (int i = 0; i < 6; i++) {
        int c = lane + i * 32;
        if (c < Cc) dst[c] = (vals[i] - mean) * rstd * g[c] + b[c];
    }
}

// ---------------- LN2 (natural layout) ----------------
__global__ void ln2_k(const float* __restrict__ y,
                      const float* __restrict__ g,
                      const float* __restrict__ b,
                      float* __restrict__ h2)
{
    int warp = (blockIdx.x * blockDim.x + threadIdx.x) >> 5;
    int lane = threadIdx.x & 31;
    if (warp >= NTOK) return;
    const float* src = y + (size_t)warp * Cc;
    float vals[6];
    float sum = 0.f, sq = 0.f;
#pragma unroll
    for (int i = 0; i < 6; i++) {
        int c = lane + i * 32;
        float v = (c < Cc) ? src[c] : 0.f;
        vals[i] = v; sum += v; sq += v * v;
    }
#pragma unroll
    for (int o = 16; o; o >>= 1) {
        sum += __shfl_xor_sync(0xffffffffu, sum, o);
        sq  += __shfl_xor_sync(0xffffffffu, sq, o);
    }
    float mean = sum * (1.f / Cc);
    float var  = sq * (1.f / Cc) - mean * mean;
    float rstd = rsqrtf(var + 1e-5f);
    float* dst = h2 + (size_t)warp * Cc;
#pragma unroll
    for (int i = 0; i < 6; i++) {
        int c = lane + i * 32;
        if (c < Cc) dst[c] = (vals[i] - mean) * rstd * g[c] + b[c];
    }
}

// ---------------- tiled fp32 GEMM: C = (A [+pb]) @ B + bias [+resid] ----------------
// A: [M,K] row-major, B: [K,N] row-major. pb (optional): [64,K], added as pb[(row&63)][k].
#define BM 64
#define BN 64
#define BK 16
__global__ __launch_bounds__(256)
void gemm_k(const float* __restrict__ A, const float* __restrict__ Bw,
            const float* __restrict__ bias, const float* __restrict__ pb,
            const float* __restrict__ resid, float* __restrict__ C,
            int M, int N, int K)
{
    __shared__ float As[BK][BM + 4];
    __shared__ float Bs[BK][BN + 4];
    int bx = blockIdx.x, by = blockIdx.y;
    int tid = threadIdx.x;
    int tx = tid & 15, ty = tid >> 4;
    int row0 = by * BM + ty * 4;
    int col0 = bx * BN + tx * 4;

    float acc[4][4] = {};
    for (int k0 = 0; k0 < K; k0 += BK) {
        // A tile: 64x16, 4 elems/thread
        {
            int r = tid >> 2;
            int c = (tid & 3) * 4;
            int gr = by * BM + r;
            const float* arow = A + (size_t)gr * K;
            const float* prow = pb ? (pb + (size_t)(gr & 63) * K) : nullptr;
#pragma unroll
            for (int i = 0; i < 4; i++) {
                int gk = k0 + c + i;
                float v = 0.f;
                if (gr < M && gk < K) {
                    v = arow[gk];
                    if (prow) v += prow[gk];
                }
                As[c + i][r] = v;
            }
        }
        // B tile: 16x64, 4 elems/thread
        {
            int r = tid >> 4;
            int c = (tid & 15) * 4;
            int gk = k0 + r;
#pragma unroll
            for (int i = 0; i < 4; i++) {
                int gc = bx * BN + c + i;
                float v = 0.f;
                if (gk < K && gc < N) v = Bw[(size_t)gk * N + gc];
                Bs[r][c + i] = v;
            }
        }
        __syncthreads();
#pragma unroll
        for (int kk = 0; kk < BK; kk++) {
            float4 a4 = *reinterpret_cast<const float4*>(&As[kk][ty * 4]);
            float4 b4 = *reinterpret_cast<const float4*>(&Bs[kk][tx * 4]);
            float a[4] = {a4.x, a4.y, a4.z, a4.w};
            float bb[4] = {b4.x, b4.y, b4.z, b4.w};
#pragma unroll
            for (int i = 0; i < 4; i++)
#pragma unroll
                for (int j = 0; j < 4; j++)
                    acc[i][j] += a[i] * bb[j];
        }
        __syncthreads();
    }
#pragma unroll
    for (int i = 0; i < 4; i++) {
        int gr = row0 + i;
        if (gr >= M) continue;
#pragma unroll
        for (int j = 0; j < 4; j++) {
            int gc = col0 + j;
            if (gc >= N) continue;
            float v = acc[i][j];
            if (bias)  v += bias[gc];
            if (resid) v += resid[(size_t)gr * N + gc];
            C[(size_t)gr * N + gc] = v;
        }
    }
}

// ---------------- self-attention: one query per thread, online softmax ----------------
__global__ __launch_bounds__(128)
void attn_self_k(const float* __restrict__ qkv,   // [NTOK, 540]
                 const float* __restrict__ mask,  // [768,128,128]
                 const float* __restrict__ rpb,   // [675,6]
                 const int*   __restrict__ rpi,   // [128,128]
                 float* __restrict__ xo)          // [NTOK,360], write cols [180,360)
{
    int win = blockIdx.x;
    int h   = blockIdx.y;
    int tid = threadIdx.x;  // query index
    __shared__ float Ks[Nn][HDd];
    __shared__ float Vs[Nn][HDd];
    const float* base = qkv + (size_t)win * Nn * (3 * Cc);

    for (int idx = tid; idx < Nn * HDd; idx += 128) {
        int j = idx / HDd, d = idx % HDd;
        Ks[j][d] = base[j * (3 * Cc) + Cc     + h * HDd + d];
        Vs[j][d] = base[j * (3 * Cc) + 2 * Cc + h * HDd + d];
    }
    __syncthreads();

    float q[HDd];
#pragma unroll
    for (int d = 0; d < HDd; d++) q[d] = base[tid * (3 * Cc) + h * HDd + d] * SCALEF;

    const float* mrow = mask + (size_t)win * (Nn * Nn) + tid * Nn;
    const int*   rrow = rpi + tid * Nn;

    float m = -1e30f, s = 0.f;
    for (int j = 0; j < Nn; j++) {
        float dot = 0.f;
#pragma unroll
        for (int d = 0; d < HDd; d++) dot += q[d] * Ks[j][d];
        dot += rpb[rrow[j] * NHh + h] + mrow[j];
        if (dot > m) { s = s * __expf(m - dot) + 1.f; m = dot; }
        else          s += __expf(dot - m);
    }
    float o[HDd];
#pragma unroll
    for (int d = 0; d < HDd; d++) o[d] = 0.f;
    for (int j = 0; j < Nn; j++) {
        float dot = 0.f;
#pragma unroll
        for (int d = 0; d < HDd; d++) dot += q[d] * Ks[j][d];
        dot += rpb[rrow[j] * NHh + h] + mrow[j];
        float p = __expf(dot - m);
#pragma unroll
        for (int d = 0; d < HDd; d++) o[d] += p * Vs[j][d];
    }
    float inv = 1.f / s;
    float* orow = xo + (size_t)(win * Nn + tid) * (2 * Cc) + Cc + h * HDd;
#pragma unroll
    for (int d = 0; d < HDd; d++) orow[d] = o[d] * inv;
}

// ---------------- mutual attention (two 64x64 halves) ----------------
__global__ __launch_bounds__(64)
void attn_mut_k(const float* __restrict__ qkv,   // [NTOK, 540]
                const float* __restrict__ mask,  // [768,128,128] (use [:64,:64])
                float* __restrict__ xo)          // [NTOK,360], write cols [0,180)
{
    int win  = blockIdx.x;
    int h    = blockIdx.y;
    int part = blockIdx.z;  // 0: x1 = attn(q[64:],k[:64],v[:64]); 1: x2 = attn(q[:64],k[64:],v[64:])
    int tid  = threadIdx.x; // local query index 0..63
    __shared__ float Ks[64][HDd];
    __shared__ float Vs[64][HDd];
    int kvoff = (part == 0) ? 0 : 64;
    int qoff  = (part == 0) ? 64 : 0;
    const float* base = qkv + (size_t)win * Nn * (3 * Cc);

    for (int idx = tid; idx < 64 * HDd; idx += 64) {
        int j = idx / HDd, d = idx % HDd;
        Ks[j][d] = base[(kvoff + j) * (3 * Cc) + Cc     + h * HDd + d];
        Vs[j][d] = base[(kvoff + j) * (3 * Cc) + 2 * Cc + h * HDd + d];
    }
    __syncthreads();

    float q[HDd];
#pragma unroll
    for (int d = 0; d < HDd; d++) q[d] = base[(qoff + tid) * (3 * Cc) + h * HDd + d] * SCALEF;

    const float* mrow = mask + (size_t)win * (Nn * Nn) + tid * Nn;  // rows/cols < 64

    float m = -1e30f, s = 0.f;
    for (int j = 0; j < 64; j++) {
        float dot = 0.f;
#pragma unroll
        for (int d = 0; d < HDd; d++) dot += q[d] * Ks[j][d];
        dot += mrow[j];
        if (dot > m) { s = s * __expf(m - dot) + 1.f; m = dot; }
        else          s += __expf(dot - m);
    }
    float o[HDd];
#pragma unroll
    for (int d = 0; d < HDd; d++) o[d] = 0.f;
    for (int j = 0; j < 64; j++) {
        float dot = 0.f;
#pragma unroll
        for (int d = 0; d < HDd; d++) dot += q[d] * Ks[j][d];
        dot += mrow[j];
        float p = __expf(dot - m);
#pragma unroll
        for (int d = 0; d < HDd; d++) o[d] += p * Vs[j][d];
    }
    float inv = 1.f / s;
    float* orow = xo + (size_t)(win * Nn + part * 64 + tid) * (2 * Cc) + h * HDd;
#pragma unroll
    for (int d = 0; d < HDd; d++) orow[d] = o[d] * inv;
}

// ---------------- scatter proj output back (win_rev + roll) + residual ----------------
__global__ void scatter_res_k(const float* __restrict__ x,
                              const float* __restrict__ proj,
                              float* __restrict__ y)
{
    size_t i = (size_t)blockIdx.x * blockDim.x + threadIdx.x;
    if (i >= (size_t)NTOK * Cc) return;
    int c = (int)(i % Cc);
    int t = (int)(i / Cc);  // rolled token
    int dp = t / (Hh * Ww);
    int rem = t % (Hh * Ww);
    int hp = rem >> 7, wp = rem & 127;
    int sd = dp + 1; if (sd >= Dd) sd -= Dd;
    int sh = (hp + 4) & 127;
    int sw = (wp + 4) & 127;
    int win = (dp >> 1) * 256 + (hp >> 3) * 16 + (wp >> 3);
    int tok = (dp & 1) * 64 + (hp & 7) * 8 + (wp & 7);
    size_t oidx = ((size_t)(sd * Hh + sh) * Ww + sw) * Cc + c;
    y[oidx] = x[oidx] + proj[(size_t)(win * Nn + tok) * Cc + c];
}

// ---------------- GEGLU elementwise: hid = gelu_exact(a1) * a2 ----------------
__global__ void geglu_k(const float* __restrict__ a1,
                        const float* __restrict__ a2,
                        float* __restrict__ hid, size_t n)
{
    size_t i = (size_t)blockIdx.x * blockDim.x + threadIdx.x;
    if (i >= n) return;
    float v = a1[i];
    float ge = 0.5f * v * (1.f + erff(v * 0.70710678118654752f));
    hid[i] = ge * a2[i];
}

// ---------------- launch ----------------
extern "C" void kernel_launch(void* const* d_in, const int* in_sizes, int n_in,
                              void* d_out, int out_size)
{
    const float* x        = (const float*)d_in[0];
    const float* mask     = (const float*)d_in[1];
    const float* g1       = (const float*)d_in[2];
    const float* b1       = (const float*)d_in[3];
    const float* g2       = (const float*)d_in[4];
    const float* b2       = (const float*)d_in[5];
    const float* w_qkv_s  = (const float*)d_in[6];
    const float* b_qkv_s  = (const float*)d_in[7];
    const float* w_qkv_m  = (const float*)d_in[8];
    const float* b_qkv_m  = (const float*)d_in[9];
    const float* rpb      = (const float*)d_in[10];
    const float* pos_bias = (const float*)d_in[11];
    const float* w_proj   = (const float*)d_in[12];
    const float* b_proj   = (const float*)d_in[13];
    const float* w_fc11   = (const float*)d_in[14];
    const float* b_fc11   = (const float*)d_in[15];
    const float* w_fc12   = (const float*)d_in[16];
    const float* b_fc12   = (const float*)d_in[17];
    const float* w_fc2    = (const float*)d_in[18];
    const float* b_fc2    = (const float*)d_in[19];
    const int*   rpi      = (const int*)d_in[20];
    float* out = (float*)d_out;

    float *p_xw, *p_qkvs, *p_qkvm, *p_xo, *p_proj, *p_y, *p_h2, *p_a1, *p_a2, *p_hid;
    cudaGetSymbolAddress((void**)&p_xw,   g_xw);
    cudaGetSymbolAddress((void**)&p_qkvs, g_qkvs);
    cudaGetSymbolAddress((void**)&p_qkvm, g_qkvm);
    cudaGetSymbolAddress((void**)&p_xo,   g_xo);
    cudaGetSymbolAddress((void**)&p_proj, g_proj);
    cudaGetSymbolAddress((void**)&p_y,    g_y);
    cudaGetSymbolAddress((void**)&p_h2,   g_h2);
    cudaGetSymbolAddress((void**)&p_a1,   g_a1);
    cudaGetSymbolAddress((void**)&p_a2,   g_a2);
    cudaGetSymbolAddress((void**)&p_hid,  g_hid);

    const int M = NTOK;

    // 1) LN1 + roll + window partition
    ln1_window_k<<<(NTOK * 32 + 255) / 256, 256>>>(x, g1, b1, p_xw);

    // 2) qkv self: [M,180] @ [180,540]
    gemm_k<<<dim3((3 * Cc + BN - 1) / BN, M / BM), 256>>>(
        p_xw, w_qkv_s, b_qkv_s, nullptr, nullptr, p_qkvs, M, 3 * Cc, Cc);

    // 3) qkv mutual: (xw + pb) @ [180,540]
    gemm_k<<<dim3((3 * Cc + BN - 1) / BN, M / BM), 256>>>(
        p_xw, w_qkv_m, b_qkv_m, pos_bias, nullptr, p_qkvm, M, 3 * Cc, Cc);

    // 4) self attention -> xo[:,180:360]
    attn_self_k<<<dim3(NWIN, NHh), 128>>>(p_qkvs, mask, rpb, rpi, p_xo);

    // 5) mutual attention -> xo[:,0:180]
    attn_mut_k<<<dim3(NWIN, NHh, 2), 64>>>(p_qkvm, mask, p_xo);

    // 6) proj: [M,360] @ [360,180]
    gemm_k<<<dim3((Cc + BN - 1) / BN, M / BM), 256>>>(
        p_xo, w_proj, b_proj, nullptr, nullptr, p_proj, M, Cc, 2 * Cc);

    // 7) win_rev + roll + residual -> y
    scatter_res_k<<<(int)(((size_t)NTOK * Cc + 255) / 256), 256>>>(x, p_proj, p_y);

    // 8) LN2
    ln2_k<<<(NTOK * 32 + 255) / 256, 256>>>(p_y, g2, b2, p_h2);

    // 9) fc11: [M,180] @ [180,360]
    gemm_k<<<dim3((HIDd + BN - 1) / BN, M / BM), 256>>>(
        p_h2, w_fc11, b_fc11, nullptr, nullptr, p_a1, M, HIDd, Cc);

    // 10) fc12
    gemm_k<<<dim3((HIDd + BN - 1) / BN, M / BM), 256>>>(
        p_h2, w_fc12, b_fc12, nullptr, nullptr, p_a2, M, HIDd, Cc);

    // 11) GEGLU
    geglu_k<<<(int)(((size_t)NTOK * HIDd + 255) / 256), 256>>>(
        p_a1, p_a2, p_hid, (size_t)NTOK * HIDd);

    // 12) fc2 + residual -> d_out: [M,360] @ [360,180] + y
    gemm_k<<<dim3((Cc + BN - 1) / BN, M / BM), 256>>>(
        p_hid, w_fc2, b_fc2, nullptr, p_y, out, M, Cc, HIDd);

    (void)in_sizes; (void)n_in; (void)out_size;
}

// round 6
// speedup vs baseline: 1.2559x; 1.2559x over previous
#include <cuda_runtime.h>
#include <cuda_bf16.h>
#include <math.h>

// ---------------- problem constants ----------------
#define Dd 6
#define Hh 128
#define Ww 128
#define Cc 180
#define NHh 6
#define HDd 30
#define Nn 128            // tokens per window
#define NWIN 768
#define NTOK (NWIN * Nn)  // 98304
#define HIDd 360
#define SCALEF 0.18257418583505536f

// ---------------- scratch ----------------
__device__ float g_xw  [NTOK * Cc];
__device__ float g_qkvs[NTOK * 3 * Cc];
__device__ float g_qkvm[NTOK * 3 * Cc];
__device__ float g_xo  [NTOK * 2 * Cc];
__device__ float g_proj[NTOK * Cc];
__device__ float g_y   [NTOK * Cc];
__device__ float g_h2  [NTOK * Cc];
__device__ float g_a1  [NTOK * HIDd];
__device__ float g_a2  [NTOK * HIDd];
__device__ float g_hid [NTOK * HIDd];

__device__ __forceinline__ unsigned f2tf32(float f) {
    unsigned u;
    asm("cvt.rna.tf32.f32 %0, %1;" : "=r"(u) : "f"(f));
    return u;
}

// ---------------- LN1 + roll + window partition ----------------
__global__ void ln1_window_k(const float* __restrict__ x,
                             const float* __restrict__ g,
                             const float* __restrict__ b,
                             float* __restrict__ xw)
{
    int warp = (blockIdx.x * blockDim.x + threadIdx.x) >> 5;
    int lane = threadIdx.x & 31;
    if (warp >= NTOK) return;
    int dp = warp / (Hh * Ww);
    int rem = warp % (Hh * Ww);
    int hp = rem >> 7;
    int wp = rem & 127;
    int sd = dp + 1; if (sd >= Dd) sd -= Dd;
    int sh = (hp + 4) & 127;
    int sw = (wp + 4) & 127;
    const float* src = x + ((size_t)(sd * Hh + sh) * Ww + sw) * Cc;

    float vals[6];
    float sum = 0.f, sq = 0.f;
#pragma unroll
    for (int i = 0; i < 6; i++) {
        int c = lane + i * 32;
        float v = (c < Cc) ? src[c] : 0.f;
        vals[i] = v; sum += v; sq += v * v;
    }
#pragma unroll
    for (int o = 16; o; o >>= 1) {
        sum += __shfl_xor_sync(0xffffffffu, sum, o);
        sq  += __shfl_xor_sync(0xffffffffu, sq, o);
    }
    float mean = sum * (1.f / Cc);
    float var  = sq * (1.f / Cc) - mean * mean;
    float rstd = rsqrtf(var + 1e-5f);

    int win = (dp >> 1) * 256 + (hp >> 3) * 16 + (wp >> 3);
    int tok = (dp & 1) * 64 + (hp & 7) * 8 + (wp & 7);
    float* dst = xw + (size_t)(win * Nn + tok) * Cc;
#pragma unroll
    for (int i = 0; i < 6; i++) {
        int c = lane + i * 32;
        if (c < Cc) dst[c] = (vals[i] - mean) * rstd * g[c] + b[c];
    }
}

// ---------------- LN2 ----------------
__global__ void ln2_k(const float* __restrict__ y,
                      const float* __restrict__ g,
                      const float* __restrict__ b,
                      float* __restrict__ h2)
{
    int warp = (blockIdx.x * blockDim.x + threadIdx.x) >> 5;
    int lane = threadIdx.x & 31;
    if (warp >= NTOK) return;
    const float* src = y + (size_t)warp * Cc;
    float vals[6];
    float sum = 0.f, sq = 0.f;
#pragma unroll
    for (int i = 0; i < 6; i++) {
        int c = lane + i * 32;
        float v = (c < Cc) ? src[c] : 0.f;
        vals[i] = v; sum += v; sq += v * v;
    }
#pragma unroll
    for (int o = 16; o; o >>= 1) {
        sum += __shfl_xor_sync(0xffffffffu, sum, o);
        sq  += __shfl_xor_sync(0xffffffffu, sq, o);
    }
    float mean = sum * (1.f / Cc);
    float var  = sq * (1.f / Cc) - mean * mean;
    float rstd = rsqrtf(var + 1e-5f);
    float* dst = h2 + (size_t)warp * Cc;
#pragma unroll
    for (int i = 0; i < 6; i++) {
        int c = lane + i * 32;
        if (c < Cc) dst[c] = (vals[i] - mean) * rstd * g[c] + b[c];
    }
}

// ---------------- TF32 tensor-core GEMM ----------------
// C[M,N] = (A[M,K] [+pb[(row&63),K]]) @ B[K,N] + bias [+resid]
// CTA tile 128x64, 8 warps (4m x 2n), warp tile 32x32, K-stage 32.
#define GBM 128
#define GBN 64
#define GBK 32
#define A_PAD 36
#define B_PAD 72

__global__ __launch_bounds__(256)
void gemm_tf32_k(const float* __restrict__ A, const float* __restrict__ Bw,
                 const float* __restrict__ bias, const float* __restrict__ pb,
                 const float* __restrict__ resid, float* __restrict__ C,
                 int M, int N, int K)
{
    __shared__ unsigned As[GBM * A_PAD];   // [m][k], pad 36
    __shared__ unsigned Bs[GBK * B_PAD];   // [k][n], pad 72

    int tid  = threadIdx.x;
    int lane = tid & 31;
    int warp = tid >> 5;
    int wm = warp & 3;        // 0..3 -> m offset wm*32
    int wn = warp >> 2;       // 0..1 -> n offset wn*32
    int g = lane >> 2;        // 0..7
    int t = lane & 3;         // 0..3

    int bx = blockIdx.x, by = blockIdx.y;
    int rowBase = by * GBM;
    int colBase = bx * GBN;

    float acc[2][4][4];
#pragma unroll
    for (int mi = 0; mi < 2; mi++)
#pragma unroll
        for (int ni = 0; ni < 4; ni++)
#pragma unroll
            for (int e = 0; e < 4; e++) acc[mi][ni][e] = 0.f;

    for (int k0 = 0; k0 < K; k0 += GBK) {
        // ---- load A tile (128x32): 4 float4 per thread ----
#pragma unroll
        for (int i = 0; i < 4; i++) {
            int f   = tid + i * 256;       // 0..1023
            int r   = f >> 3;              // 0..127
            int k4  = (f & 7) * 4;         // 0,4,..28
            int gr  = rowBase + r;
            int gk0 = k0 + k4;
            const float* arow = A + (size_t)gr * K;
            float v0, v1, v2, v3;
            if (gk0 + 3 < K) {
                float4 a4 = *reinterpret_cast<const float4*>(arow + gk0);
                v0 = a4.x; v1 = a4.y; v2 = a4.z; v3 = a4.w;
            } else {
                v0 = (gk0 + 0 < K) ? arow[gk0 + 0] : 0.f;
                v1 = (gk0 + 1 < K) ? arow[gk0 + 1] : 0.f;
                v2 = (gk0 + 2 < K) ? arow[gk0 + 2] : 0.f;
                v3 = (gk0 + 3 < K) ? arow[gk0 + 3] : 0.f;
            }
            if (pb) {
                const float* prow = pb + (size_t)(gr & 63) * K;
                if (gk0 + 3 < K) {
                    float4 p4 = *reinterpret_cast<const float4*>(prow + gk0);
                    v0 += p4.x; v1 += p4.y; v2 += p4.z; v3 += p4.w;
                } else {
                    if (gk0 + 0 < K) v0 += prow[gk0 + 0];
                    if (gk0 + 1 < K) v1 += prow[gk0 + 1];
                    if (gk0 + 2 < K) v2 += prow[gk0 + 2];
                    if (gk0 + 3 < K) v3 += prow[gk0 + 3];
                }
            }
            unsigned* dst = &As[r * A_PAD + k4];
            dst[0] = f2tf32(v0); dst[1] = f2tf32(v1);
            dst[2] = f2tf32(v2); dst[3] = f2tf32(v3);
        }
        // ---- load B tile (32x64): 8 scalars per thread ----
#pragma unroll
        for (int i = 0; i < 2; i++) {
            int f   = tid + i * 256;       // 0..511 (of 512 float4-groups)
            int kr  = f >> 4;              // 0..31
            int n4  = (f & 15) * 4;        // 0..60
            int gk  = k0 + kr;
            unsigned* dst = &Bs[kr * B_PAD + n4];
            if (gk < K) {
                const float* brow = Bw + (size_t)gk * N + colBase + n4;
#pragma unroll
                for (int c = 0; c < 4; c++) {
                    int gc = colBase + n4 + c;
                    dst[c] = (gc < N) ? f2tf32(__ldg(brow + c)) : 0u;
                }
            } else {
                dst[0] = dst[1] = dst[2] = dst[3] = 0u;
            }
        }
        __syncthreads();

        // ---- mma over 4 k-steps of 8 ----
#pragma unroll
        for (int kk = 0; kk < GBK; kk += 8) {
            unsigned afr[2][4];
#pragma unroll
            for (int mi = 0; mi < 2; mi++) {
                int r0 = wm * 32 + mi * 16;
                afr[mi][0] = As[(r0 + g)     * A_PAD + kk + t];
                afr[mi][1] = As[(r0 + g + 8) * A_PAD + kk + t];
                afr[mi][2] = As[(r0 + g)     * A_PAD + kk + t + 4];
                afr[mi][3] = As[(r0 + g + 8) * A_PAD + kk + t + 4];
            }
            unsigned bfr[4][2];
#pragma unroll
            for (int ni = 0; ni < 4; ni++) {
                int c0 = wn * 32 + ni * 8 + g;
                bfr[ni][0] = Bs[(kk + t)     * B_PAD + c0];
                bfr[ni][1] = Bs[(kk + t + 4) * B_PAD + c0];
            }
#pragma unroll
            for (int mi = 0; mi < 2; mi++)
#pragma unroll
                for (int ni = 0; ni < 4; ni++) {
                    asm volatile(
                        "mma.sync.aligned.m16n8k8.row.col.f32.tf32.tf32.f32 "
                        "{%0,%1,%2,%3}, {%4,%5,%6,%7}, {%8,%9}, {%0,%1,%2,%3};"
                        : "+f"(acc[mi][ni][0]), "+f"(acc[mi][ni][1]),
                          "+f"(acc[mi][ni][2]), "+f"(acc[mi][ni][3])
                        : "r"(afr[mi][0]), "r"(afr[mi][1]),
                          "r"(afr[mi][2]), "r"(afr[mi][3]),
                          "r"(bfr[ni][0]), "r"(bfr[ni][1]));
                }
        }
        __syncthreads();
    }

    // ---- epilogue ----
#pragma unroll
    for (int mi = 0; mi < 2; mi++) {
#pragma unroll
        for (int ni = 0; ni < 4; ni++) {
#pragma unroll
            for (int half = 0; half < 2; half++) {
                int gr = rowBase + wm * 32 + mi * 16 + g + half * 8;
                int gc0 = colBase + wn * 32 + ni * 8 + 2 * t;
                float v0 = acc[mi][ni][half * 2 + 0];
                float v1 = acc[mi][ni][half * 2 + 1];
                if (gc0 < N) {
                    float o = v0;
                    if (bias)  o += bias[gc0];
                    if (resid) o += resid[(size_t)gr * N + gc0];
                    C[(size_t)gr * N + gc0] = o;
                }
                if (gc0 + 1 < N) {
                    float o = v1;
                    if (bias)  o += bias[gc0 + 1];
                    if (resid) o += resid[(size_t)gr * N + gc0 + 1];
                    C[(size_t)gr * N + gc0 + 1] = o;
                }
            }
        }
    }
}

// ---------------- self-attention ----------------
__global__ __launch_bounds__(128)
void attn_self_k(const float* __restrict__ qkv,
                 const float* __restrict__ mask,
                 const float* __restrict__ rpb,
                 const int*   __restrict__ rpi,
                 float* __restrict__ xo)
{
    int win = blockIdx.x;
    int h   = blockIdx.y;
    int tid = threadIdx.x;
    __shared__ float Ks[Nn][HDd];
    __shared__ float Vs[Nn][HDd];
    const float* base = qkv + (size_t)win * Nn * (3 * Cc);

    for (int idx = tid; idx < Nn * HDd; idx += 128) {
        int j = idx / HDd, d = idx % HDd;
        Ks[j][d] = base[j * (3 * Cc) + Cc     + h * HDd + d];
        Vs[j][d] = base[j * (3 * Cc) + 2 * Cc + h * HDd + d];
    }
    __syncthreads();

    float q[HDd];
#pragma unroll
    for (int d = 0; d < HDd; d++) q[d] = base[tid * (3 * Cc) + h * HDd + d] * SCALEF;

    const float* mrow = mask + (size_t)win * (Nn * Nn) + tid * Nn;
    const int*   rrow = rpi + tid * Nn;

    float m = -1e30f, s = 0.f;
    for (int j = 0; j < Nn; j++) {
        float dot = 0.f;
#pragma unroll
        for (int d = 0; d < HDd; d++) dot += q[d] * Ks[j][d];
        dot += rpb[rrow[j] * NHh + h] + mrow[j];
        if (dot > m) { s = s * __expf(m - dot) + 1.f; m = dot; }
        else          s += __expf(dot - m);
    }
    float o[HDd];
#pragma unroll
    for (int d = 0; d < HDd; d++) o[d] = 0.f;
    for (int j = 0; j < Nn; j++) {
        float dot = 0.f;
#pragma unroll
        for (int d = 0; d < HDd; d++) dot += q[d] * Ks[j][d];
        dot += rpb[rrow[j] * NHh + h] + mrow[j];
        float p = __expf(dot - m);
#pragma unroll
        for (int d = 0; d < HDd; d++) o[d] += p * Vs[j][d];
    }
    float inv = 1.f / s;
    float* orow = xo + (size_t)(win * Nn + tid) * (2 * Cc) + Cc + h * HDd;
#pragma unroll
    for (int d = 0; d < HDd; d++) orow[d] = o[d] * inv;
}

// ---------------- mutual attention ----------------
__global__ __launch_bounds__(64)
void attn_mut_k(const float* __restrict__ qkv,
                const float* __restrict__ mask,
                float* __restrict__ xo)
{
    int win  = blockIdx.x;
    int h    = blockIdx.y;
    int part = blockIdx.z;
    int tid  = threadIdx.x;
    __shared__ float Ks[64][HDd];
    __shared__ float Vs[64][HDd];
    int kvoff = (part == 0) ? 0 : 64;
    int qoff  = (part == 0) ? 64 : 0;
    const float* base = qkv + (size_t)win * Nn * (3 * Cc);

    for (int idx = tid; idx < 64 * HDd; idx += 64) {
        int j = idx / HDd, d = idx % HDd;
        Ks[j][d] = base[(kvoff + j) * (3 * Cc) + Cc     + h * HDd + d];
        Vs[j][d] = base[(kvoff + j) * (3 * Cc) + 2 * Cc + h * HDd + d];
    }
    __syncthreads();

    float q[HDd];
#pragma unroll
    for (int d = 0; d < HDd; d++) q[d] = base[(qoff + tid) * (3 * Cc) + h * HDd + d] * SCALEF;

    const float* mrow = mask + (size_t)win * (Nn * Nn) + tid * Nn;

    float m = -1e30f, s = 0.f;
    for (int j = 0; j < 64; j++) {
        float dot = 0.f;
#pragma unroll
        for (int d = 0; d < HDd; d++) dot += q[d] * Ks[j][d];
        dot += mrow[j];
        if (dot > m) { s = s * __expf(m - dot) + 1.f; m = dot; }
        else          s += __expf(dot - m);
    }
    float o[HDd];
#pragma unroll
    for (int d = 0; d < HDd; d++) o[d] = 0.f;
    for (int j = 0; j < 64; j++) {
        float dot = 0.f;
#pragma unroll
        for (int d = 0; d < HDd; d++) dot += q[d] * Ks[j][d];
        dot += mrow[j];
        float p = __expf(dot - m);
#pragma unroll
        for (int d = 0; d < HDd; d++) o[d] += p * Vs[j][d];
    }
    float inv = 1.f / s;
    float* orow = xo + (size_t)(win * Nn + part * 64 + tid) * (2 * Cc) + h * HDd;
#pragma unroll
    for (int d = 0; d < HDd; d++) orow[d] = o[d] * inv;
}

// ---------------- scatter + residual ----------------
__global__ void scatter_res_k(const float* __restrict__ x,
                              const float* __restrict__ proj,
                              float* __restrict__ y)
{
    size_t i = (size_t)blockIdx.x * blockDim.x + threadIdx.x;
    if (i >= (size_t)NTOK * Cc) return;
    int c = (int)(i % Cc);
    int t = (int)(i / Cc);
    int dp = t / (Hh * Ww);
    int rem = t % (Hh * Ww);
    int hp = rem >> 7, wp = rem & 127;
    int sd = dp + 1; if (sd >= Dd) sd -= Dd;
    int sh = (hp + 4) & 127;
    int sw = (wp + 4) & 127;
    int win = (dp >> 1) * 256 + (hp >> 3) * 16 + (wp >> 3);
    int tok = (dp & 1) * 64 + (hp & 7) * 8 + (wp & 7);
    size_t oidx = ((size_t)(sd * Hh + sh) * Ww + sw) * Cc + c;
    y[oidx] = x[oidx] + proj[(size_t)(win * Nn + tok) * Cc + c];
}

// ---------------- GEGLU ----------------
__global__ void geglu_k(const float* __restrict__ a1,
                        const float* __restrict__ a2,
                        float* __restrict__ hid, size_t n)
{
    size_t i = (size_t)blockIdx.x * blockDim.x + threadIdx.x;
    if (i >= n) return;
    float v = a1[i];
    float ge = 0.5f * v * (1.f + erff(v * 0.70710678118654752f));
    hid[i] = ge * a2[i];
}

// ---------------- launch ----------------
extern "C" void kernel_launch(void* const* d_in, const int* in_sizes, int n_in,
                              void* d_out, int out_size)
{
    const float* x        = (const float*)d_in[0];
    const float* mask     = (const float*)d_in[1];
    const float* g1       = (const float*)d_in[2];
    const float* b1       = (const float*)d_in[3];
    const float* g2       = (const float*)d_in[4];
    const float* b2       = (const float*)d_in[5];
    const float* w_qkv_s  = (const float*)d_in[6];
    const float* b_qkv_s  = (const float*)d_in[7];
    const float* w_qkv_m  = (const float*)d_in[8];
    const float* b_qkv_m  = (const float*)d_in[9];
    const float* rpb      = (const float*)d_in[10];
    const float* pos_bias = (const float*)d_in[11];
    const float* w_proj   = (const float*)d_in[12];
    const float* b_proj   = (const float*)d_in[13];
    const float* w_fc11   = (const float*)d_in[14];
    const float* b_fc11   = (const float*)d_in[15];
    const float* w_fc12   = (const float*)d_in[16];
    const float* b_fc12   = (const float*)d_in[17];
    const float* w_fc2    = (const float*)d_in[18];
    const float* b_fc2    = (const float*)d_in[19];
    const int*   rpi      = (const int*)d_in[20];
    float* out = (float*)d_out;

    float *p_xw, *p_qkvs, *p_qkvm, *p_xo, *p_proj, *p_y, *p_h2, *p_a1, *p_a2, *p_hid;
    cudaGetSymbolAddress((void**)&p_xw,   g_xw);
    cudaGetSymbolAddress((void**)&p_qkvs, g_qkvs);
    cudaGetSymbolAddress((void**)&p_qkvm, g_qkvm);
    cudaGetSymbolAddress((void**)&p_xo,   g_xo);
    cudaGetSymbolAddress((void**)&p_proj, g_proj);
    cudaGetSymbolAddress((void**)&p_y,    g_y);
    cudaGetSymbolAddress((void**)&p_h2,   g_h2);
    cudaGetSymbolAddress((void**)&p_a1,   g_a1);
    cudaGetSymbolAddress((void**)&p_a2,   g_a2);
    cudaGetSymbolAddress((void**)&p_hid,  g_hid);

    const int M = NTOK;

    ln1_window_k<<<(NTOK * 32 + 255) / 256, 256>>>(x, g1, b1, p_xw);

    gemm_tf32_k<<<dim3((3 * Cc + GBN - 1) / GBN, M / GBM), 256>>>(
        p_xw, w_qkv_s, b_qkv_s, nullptr, nullptr, p_qkvs, M, 3 * Cc, Cc);

    gemm_tf32_k<<<dim3((3 * Cc + GBN - 1) / GBN, M / GBM), 256>>>(
        p_xw, w_qkv_m, b_qkv_m, pos_bias, nullptr, p_qkvm, M, 3 * Cc, Cc);

    attn_self_k<<<dim3(NWIN, NHh), 128>>>(p_qkvs, mask, rpb, rpi, p_xo);

    attn_mut_k<<<dim3(NWIN, NHh, 2), 64>>>(p_qkvm, mask, p_xo);

    gemm_tf32_k<<<dim3((Cc + GBN - 1) / GBN, M / GBM), 256>>>(
        p_xo, w_proj, b_proj, nullptr, nullptr, p_proj, M, Cc, 2 * Cc);

    scatter_res_k<<<(int)(((size_t)NTOK * Cc + 255) / 256), 256>>>(x, p_proj, p_y);

    ln2_k<<<(NTOK * 32 + 255) / 256, 256>>>(p_y, g2, b2, p_h2);

    gemm_tf32_k<<<dim3((HIDd + GBN - 1) / GBN, M / GBM), 256>>>(
        p_h2, w_fc11, b_fc11, nullptr, nullptr, p_a1, M, HIDd, Cc);

    gemm_tf32_k<<<dim3((HIDd + GBN - 1) / GBN, M / GBM), 256>>>(
        p_h2, w_fc12, b_fc12, nullptr, nullptr, p_a2, M, HIDd, Cc);

    geglu_k<<<(int)(((size_t)NTOK * HIDd + 255) / 256), 256>>>(
        p_a1, p_a2, p_hid, (size_t)NTOK * HIDd);

    gemm_tf32_k<<<dim3((Cc + GBN - 1) / GBN, M / GBM), 256>>>(
        p_hid, w_fc2, b_fc2, nullptr, p_y, out, M, Cc, HIDd);

    (void)in_sizes; (void)n_in; (void)out_size;
}

// round 7
// speedup vs baseline: 2.6947x; 2.1456x over previous
#include <cuda_runtime.h>
#include <cuda_bf16.h>
#include <math.h>

// ---------------- problem constants ----------------
#define Dd 6
#define Hh 128
#define Ww 128
#define Cc 180
#define NHh 6
#define HDd 30
#define Nn 128
#define NWIN 768
#define NTOK (NWIN * Nn)  // 98304
#define HIDd 360
#define SCALEF 0.18257418583505536f

// ---------------- scratch ----------------
__device__ float g_xw  [NTOK * Cc];
__device__ float g_xwp [NTOK * Cc];        // xw + pos_bias (for mutual qkv)
__device__ float g_qkvs[NTOK * 3 * Cc];
__device__ float g_qkvm[NTOK * 3 * Cc];
__device__ float g_xo  [NTOK * 2 * Cc];
__device__ float g_y   [NTOK * Cc];
__device__ float g_h2  [NTOK * Cc];
__device__ float g_a1  [NTOK * HIDd];

__device__ __forceinline__ unsigned smem_u32(const void* p) {
    return (unsigned)__cvta_generic_to_shared(p);
}

#define CP_ASYNC16(saddr, gptr, vb) \
    asm volatile("cp.async.ca.shared.global [%0], [%1], 16, %2;\n" \
                 :: "r"(saddr), "l"(gptr), "r"(vb))

// ---------------- LN1 + roll + window partition (+pb variant) ----------------
__global__ void ln1_window_k(const float* __restrict__ x,
                             const float* __restrict__ g,
                             const float* __restrict__ b,
                             const float* __restrict__ pb,   // [64,180]
                             float* __restrict__ xw,
                             float* __restrict__ xwp)
{
    int warp = (blockIdx.x * blockDim.x + threadIdx.x) >> 5;
    int lane = threadIdx.x & 31;
    if (warp >= NTOK) return;
    int dp = warp / (Hh * Ww);
    int rem = warp % (Hh * Ww);
    int hp = rem >> 7;
    int wp = rem & 127;
    int sd = dp + 1; if (sd >= Dd) sd -= Dd;
    int sh = (hp + 4) & 127;
    int sw = (wp + 4) & 127;
    const float* src = x + ((size_t)(sd * Hh + sh) * Ww + sw) * Cc;

    float vals[6];
    float sum = 0.f, sq = 0.f;
#pragma unroll
    for (int i = 0; i < 6; i++) {
        int c = lane + i * 32;
        float v = (c < Cc) ? src[c] : 0.f;
        vals[i] = v; sum += v; sq += v * v;
    }
#pragma unroll
    for (int o = 16; o; o >>= 1) {
        sum += __shfl_xor_sync(0xffffffffu, sum, o);
        sq  += __shfl_xor_sync(0xffffffffu, sq, o);
    }
    float mean = sum * (1.f / Cc);
    float var  = sq * (1.f / Cc) - mean * mean;
    float rstd = rsqrtf(var + 1e-5f);

    int win = (dp >> 1) * 256 + (hp >> 3) * 16 + (wp >> 3);
    int tok = (dp & 1) * 64 + (hp & 7) * 8 + (wp & 7);
    float* dst  = xw  + (size_t)(win * Nn + tok) * Cc;
    float* dstp = xwp + (size_t)(win * Nn + tok) * Cc;
    const float* prow = pb + (size_t)(tok & 63) * Cc;
#pragma unroll
    for (int i = 0; i < 6; i++) {
        int c = lane + i * 32;
        if (c < Cc) {
            float v = (vals[i] - mean) * rstd * g[c] + b[c];
            dst[c]  = v;
            dstp[c] = v + prow[c];
        }
    }
}

// ---------------- LN2 ----------------
__global__ void ln2_k(const float* __restrict__ y,
                      const float* __restrict__ g,
                      const float* __restrict__ b,
                      float* __restrict__ h2)
{
    int warp = (blockIdx.x * blockDim.x + threadIdx.x) >> 5;
    int lane = threadIdx.x & 31;
    if (warp >= NTOK) return;
    const float* src = y + (size_t)warp * Cc;
    float vals[6];
    float sum = 0.f, sq = 0.f;
#pragma unroll
    for (int i = 0; i < 6; i++) {
        int c = lane + i * 32;
        float v = (c < Cc) ? src[c] : 0.f;
        vals[i] = v; sum += v; sq += v * v;
    }
#pragma unroll
    for (int o = 16; o; o >>= 1) {
        sum += __shfl_xor_sync(0xffffffffu, sum, o);
        sq  += __shfl_xor_sync(0xffffffffu, sq, o);
    }
    float mean = sum * (1.f / Cc);
    float var  = sq * (1.f / Cc) - mean * mean;
    float rstd = rsqrtf(var + 1e-5f);
    float* dst = h2 + (size_t)warp * Cc;
#pragma unroll
    for (int i = 0; i < 6; i++) {
        int c = lane + i * 32;
        if (c < Cc) dst[c] = (vals[i] - mean) * rstd * g[c] + b[c];
    }
}

// ---------------- pipelined TF32 GEMM (cp.async double-buffered) ----------------
// C = A[M,K] @ B[K,N] + bias, epilogue modes:
//   0: none   1: scatter(win_rev+roll)+x-resid (extra=x, out natural)
//   2: geglu  (extra=a1; out = gelu(a1) * (acc+bias))
//   3: resid  (extra=y;  out = acc+bias+y)
// raw fp32 bits fed to mma.tf32 (HW truncates mantissa).
#define APITCH 20
#define BPITCH 136

__global__ __launch_bounds__(256, 2)
void gemm_cp_k(const float* __restrict__ A, const float* __restrict__ Bw,
               const float* __restrict__ bias, const float* __restrict__ extra,
               float* __restrict__ Cout, int M, int N, int K, int mode)
{
    __shared__ float As[2][128 * APITCH];
    __shared__ float Bs[2][16 * BPITCH];

    int tid  = threadIdx.x;
    int lane = tid & 31;
    int warp = tid >> 5;
    int wmBase = (warp >> 2) * 64;
    int wnBase = (warp & 3) * 32;
    int g = lane >> 2;
    int t = lane & 3;

    int rowBase = blockIdx.y * 128;
    int colBase = blockIdx.x * 128;

    float acc[4][4][4] = {};

    unsigned asAddr[2] = { smem_u32(&As[0][0]), smem_u32(&As[1][0]) };
    unsigned bsAddr[2] = { smem_u32(&Bs[0][0]), smem_u32(&Bs[1][0]) };

    int nk = (K + 15) >> 4;

    auto loadStage = [&](int s, int k0) {
#pragma unroll
        for (int i = 0; i < 2; i++) {
            int ch = tid + i * 256;          // 0..511
            int r  = ch >> 2;
            int kc = (ch & 3) * 4;
            int gk = k0 + kc;
            bool ok = (gk < K);              // K % 4 == 0 -> whole chunk valid
            const float* src = ok ? (A + (size_t)(rowBase + r) * K + gk) : A;
            int vb = ok ? 16 : 0;
            CP_ASYNC16(asAddr[s] + (unsigned)(r * APITCH + kc) * 4u, src, vb);
        }
#pragma unroll
        for (int i = 0; i < 2; i++) {
            int ch = tid + i * 256;          // 0..511
            int kr = ch >> 5;
            int nc = (ch & 31) * 4;
            int gk = k0 + kr;
            int gc = colBase + nc;
            bool ok = (gk < K) && (gc < N);  // N % 4 == 0
            const float* src = ok ? (Bw + (size_t)gk * N + gc) : Bw;
            int vb = ok ? 16 : 0;
            CP_ASYNC16(bsAddr[s] + (unsigned)(kr * BPITCH + nc) * 4u, src, vb);
        }
    };

    loadStage(0, 0);
    asm volatile("cp.async.commit_group;\n");

    for (int it = 0; it < nk; ++it) {
        if (it + 1 < nk) {
            loadStage((it + 1) & 1, (it + 1) * 16);
            asm volatile("cp.async.commit_group;\n");
            asm volatile("cp.async.wait_group 1;\n");
        } else {
            asm volatile("cp.async.wait_group 0;\n");
        }
        __syncthreads();

        const float* as = As[it & 1];
        const float* bs = Bs[it & 1];
#pragma unroll
        for (int kk = 0; kk < 16; kk += 8) {
            unsigned afr[4][4], bfr[4][2];
#pragma unroll
            for (int mi = 0; mi < 4; mi++) {
                const float* pa = as + (wmBase + mi * 16 + g) * APITCH + kk + t;
                afr[mi][0] = __float_as_uint(pa[0]);
                afr[mi][1] = __float_as_uint(pa[8 * APITCH]);
                afr[mi][2] = __float_as_uint(pa[4]);
                afr[mi][3] = __float_as_uint(pa[8 * APITCH + 4]);
            }
#pragma unroll
            for (int ni = 0; ni < 4; ni++) {
                const float* pbp = bs + (kk + t) * BPITCH + wnBase + ni * 8 + g;
                bfr[ni][0] = __float_as_uint(pbp[0]);
                bfr[ni][1] = __float_as_uint(pbp[4 * BPITCH]);
            }
#pragma unroll
            for (int mi = 0; mi < 4; mi++)
#pragma unroll
                for (int ni = 0; ni < 4; ni++) {
                    asm volatile(
                        "mma.sync.aligned.m16n8k8.row.col.f32.tf32.tf32.f32 "
                        "{%0,%1,%2,%3}, {%4,%5,%6,%7}, {%8,%9}, {%0,%1,%2,%3};"
                        : "+f"(acc[mi][ni][0]), "+f"(acc[mi][ni][1]),
                          "+f"(acc[mi][ni][2]), "+f"(acc[mi][ni][3])
                        : "r"(afr[mi][0]), "r"(afr[mi][1]),
                          "r"(afr[mi][2]), "r"(afr[mi][3]),
                          "r"(bfr[ni][0]), "r"(bfr[ni][1]));
                }
        }
        __syncthreads();
    }

    // ---- epilogue ----
#pragma unroll
    for (int mi = 0; mi < 4; mi++) {
#pragma unroll
        for (int half = 0; half < 2; half++) {
            int gr = rowBase + wmBase + mi * 16 + g + half * 8;
            size_t obase;
            if (mode == 1) {
                int win = gr >> 7, tok = gr & 127;
                int dp  = (win >> 8) * 2 + (tok >> 6);
                int rem = win & 255;
                int hp  = (rem >> 4) * 8 + ((tok >> 3) & 7);
                int wp  = (rem & 15) * 8 + (tok & 7);
                int sd = dp + 1; if (sd >= Dd) sd -= Dd;
                int sh = (hp + 4) & 127;
                int sw = (wp + 4) & 127;
                obase = ((size_t)(sd * Hh + sh) * Ww + sw) * (size_t)Cc;
            } else {
                obase = (size_t)gr * N;
            }
#pragma unroll
            for (int ni = 0; ni < 4; ni++) {
#pragma unroll
                for (int e = 0; e < 2; e++) {
                    int gc = colBase + wnBase + ni * 8 + 2 * t + e;
                    if (gc >= N) continue;
                    float v = acc[mi][ni][half * 2 + e] + bias[gc];
                    if (mode == 1) {
                        v += extra[obase + gc];
                    } else if (mode == 2) {
                        float a = extra[(size_t)gr * N + gc];
                        v *= 0.5f * a * (1.f + erff(a * 0.70710678118654752f));
                    } else if (mode == 3) {
                        v += extra[(size_t)gr * N + gc];
                    }
                    Cout[obase + gc] = v;
                }
            }
        }
    }
}

// ---------------- self-attention: single-pass softmax, float2 ----------------
__global__ __launch_bounds__(128)
void attn_self_k(const float* __restrict__ qkv,   // [NTOK, 540]
                 const float* __restrict__ mask,  // [768,128,128]
                 const float* __restrict__ rpb,   // [675,6]
                 const int*   __restrict__ rpi,   // [128,128]
                 float* __restrict__ xo)          // [NTOK,360] cols [180,360)
{
    int h   = blockIdx.x;
    int win = blockIdx.y;
    int tid = threadIdx.x;
    __shared__ float Ks[Nn * HDd];
    __shared__ float Vs[Nn * HDd];
    __shared__ float rpbs[675];
    const float* base = qkv + (size_t)win * Nn * (3 * Cc);

    for (int idx = tid; idx < 675; idx += 128) rpbs[idx] = rpb[idx * NHh + h];
    // vectorized K/V stage: 1920 float2 each
    for (int i2 = tid; i2 < Nn * 15; i2 += 128) {
        int j = i2 / 15, d2 = i2 % 15;
        const float2* ksrc = (const float2*)(base + j * (3 * Cc) + Cc     + h * HDd) + d2;
        const float2* vsrc = (const float2*)(base + j * (3 * Cc) + 2 * Cc + h * HDd) + d2;
        ((float2*)Ks)[j * 15 + d2] = *ksrc;
        ((float2*)Vs)[j * 15 + d2] = *vsrc;
    }
    __syncthreads();

    float2 q2[15];
    const float2* qsrc = (const float2*)(base + tid * (3 * Cc) + h * HDd);
#pragma unroll
    for (int d = 0; d < 15; d++) {
        q2[d] = qsrc[d];
        q2[d].x *= SCALEF; q2[d].y *= SCALEF;
    }

    const float* mrow = mask + (size_t)win * (Nn * Nn) + tid * Nn;
    const int*   rrow = rpi + tid * Nn;

    float s = 0.f;
    float2 o2[15];
#pragma unroll
    for (int d = 0; d < 15; d++) o2[d] = make_float2(0.f, 0.f);

    for (int j = 0; j < Nn; j++) {
        const float2* kr = ((const float2*)Ks) + j * 15;
        float dot = 0.f;
#pragma unroll
        for (int d = 0; d < 15; d++) dot += q2[d].x * kr[d].x + q2[d].y * kr[d].y;
        float sc = dot + rpbs[rrow[j]] + mrow[j];
        float p = __expf(fminf(sc, 60.f));
        s += p;
        const float2* vr = ((const float2*)Vs) + j * 15;
#pragma unroll
        for (int d = 0; d < 15; d++) {
            o2[d].x += p * vr[d].x;
            o2[d].y += p * vr[d].y;
        }
    }
    float inv = 1.f / s;
    float2* orow = (float2*)(xo + (size_t)(win * Nn + tid) * (2 * Cc) + Cc + h * HDd);
#pragma unroll
    for (int d = 0; d < 15; d++) {
        orow[d] = make_float2(o2[d].x * inv, o2[d].y * inv);
    }
}

// ---------------- mutual attention: single-pass, float2 ----------------
__global__ __launch_bounds__(64)
void attn_mut_k(const float* __restrict__ qkv,
                const float* __restrict__ mask,
                float* __restrict__ xo)          // cols [0,180)
{
    int h    = blockIdx.x;
    int win  = blockIdx.y;
    int part = blockIdx.z;
    int tid  = threadIdx.x;
    __shared__ float Ks[64 * HDd];
    __shared__ float Vs[64 * HDd];
    int kvoff = (part == 0) ? 0 : 64;
    int qoff  = (part == 0) ? 64 : 0;
    const float* base = qkv + (size_t)win * Nn * (3 * Cc);

    for (int i2 = tid; i2 < 64 * 15; i2 += 64) {
        int j = i2 / 15, d2 = i2 % 15;
        const float2* ksrc = (const float2*)(base + (kvoff + j) * (3 * Cc) + Cc     + h * HDd) + d2;
        const float2* vsrc = (const float2*)(base + (kvoff + j) * (3 * Cc) + 2 * Cc + h * HDd) + d2;
        ((float2*)Ks)[j * 15 + d2] = *ksrc;
        ((float2*)Vs)[j * 15 + d2] = *vsrc;
    }
    __syncthreads();

    float2 q2[15];
    const float2* qsrc = (const float2*)(base + (qoff + tid) * (3 * Cc) + h * HDd);
#pragma unroll
    for (int d = 0; d < 15; d++) {
        q2[d] = qsrc[d];
        q2[d].x *= SCALEF; q2[d].y *= SCALEF;
    }

    const float* mrow = mask + (size_t)win * (Nn * Nn) + tid * Nn;

    float s = 0.f;
    float2 o2[15];
#pragma unroll
    for (int d = 0; d < 15; d++) o2[d] = make_float2(0.f, 0.f);

    for (int j = 0; j < 64; j++) {
        const float2* kr = ((const float2*)Ks) + j * 15;
        float dot = 0.f;
#pragma unroll
        for (int d = 0; d < 15; d++) dot += q2[d].x * kr[d].x + q2[d].y * kr[d].y;
        float sc = dot + mrow[j];
        float p = __expf(fminf(sc, 60.f));
        s += p;
        const float2* vr = ((const float2*)Vs) + j * 15;
#pragma unroll
        for (int d = 0; d < 15; d++) {
            o2[d].x += p * vr[d].x;
            o2[d].y += p * vr[d].y;
        }
    }
    float inv = 1.f / s;
    float2* orow = (float2*)(xo + (size_t)(win * Nn + part * 64 + tid) * (2 * Cc) + h * HDd);
#pragma unroll
    for (int d = 0; d < 15; d++) {
        orow[d] = make_float2(o2[d].x * inv, o2[d].y * inv);
    }
}

// ---------------- launch ----------------
extern "C" void kernel_launch(void* const* d_in, const int* in_sizes, int n_in,
                              void* d_out, int out_size)
{
    const float* x        = (const float*)d_in[0];
    const float* mask     = (const float*)d_in[1];
    const float* g1       = (const float*)d_in[2];
    const float* b1       = (const float*)d_in[3];
    const float* g2       = (const float*)d_in[4];
    const float* b2       = (const float*)d_in[5];
    const float* w_qkv_s  = (const float*)d_in[6];
    const float* b_qkv_s  = (const float*)d_in[7];
    const float* w_qkv_m  = (const float*)d_in[8];
    const float* b_qkv_m  = (const float*)d_in[9];
    const float* rpb      = (const float*)d_in[10];
    const float* pos_bias = (const float*)d_in[11];
    const float* w_proj   = (const float*)d_in[12];
    const float* b_proj   = (const float*)d_in[13];
    const float* w_fc11   = (const float*)d_in[14];
    const float* b_fc11   = (const float*)d_in[15];
    const float* w_fc12   = (const float*)d_in[16];
    const float* b_fc12   = (const float*)d_in[17];
    const float* w_fc2    = (const float*)d_in[18];
    const float* b_fc2    = (const float*)d_in[19];
    const int*   rpi      = (const int*)d_in[20];
    float* out = (float*)d_out;

    float *p_xw, *p_xwp, *p_qkvs, *p_qkvm, *p_xo, *p_y, *p_h2, *p_a1;
    cudaGetSymbolAddress((void**)&p_xw,   g_xw);
    cudaGetSymbolAddress((void**)&p_xwp,  g_xwp);
    cudaGetSymbolAddress((void**)&p_qkvs, g_qkvs);
    cudaGetSymbolAddress((void**)&p_qkvm, g_qkvm);
    cudaGetSymbolAddress((void**)&p_xo,   g_xo);
    cudaGetSymbolAddress((void**)&p_y,    g_y);
    cudaGetSymbolAddress((void**)&p_h2,   g_h2);
    cudaGetSymbolAddress((void**)&p_a1,   g_a1);

    const int M = NTOK;
    auto ggrid = [](int N) { return dim3((unsigned)((N + 127) / 128), NTOK / 128); };

    // 1) LN1 + roll + window partition (+ pos-bias variant)
    ln1_window_k<<<(NTOK * 32 + 255) / 256, 256>>>(x, g1, b1, pos_bias, p_xw, p_xwp);

    // 2) qkv self: [M,180]@[180,540]
    gemm_cp_k<<<ggrid(3 * Cc), 256>>>(p_xw, w_qkv_s, b_qkv_s, nullptr, p_qkvs,
                                      M, 3 * Cc, Cc, 0);
    // 3) qkv mutual (pb pre-added)
    gemm_cp_k<<<ggrid(3 * Cc), 256>>>(p_xwp, w_qkv_m, b_qkv_m, nullptr, p_qkvm,
                                      M, 3 * Cc, Cc, 0);
    // 4) self attention -> xo[:,180:360]
    attn_self_k<<<dim3(NHh, NWIN), 128>>>(p_qkvs, mask, rpb, rpi, p_xo);
    // 5) mutual attention -> xo[:,0:180]
    attn_mut_k<<<dim3(NHh, NWIN, 2), 64>>>(p_qkvm, mask, p_xo);
    // 6) proj + win_rev + roll + x residual -> y (natural layout)
    gemm_cp_k<<<ggrid(Cc), 256>>>(p_xo, w_proj, b_proj, x, p_y,
                                  M, Cc, 2 * Cc, 1);
    // 7) LN2
    ln2_k<<<(NTOK * 32 + 255) / 256, 256>>>(p_y, g2, b2, p_h2);
    // 8) fc11 -> a1
    gemm_cp_k<<<ggrid(HIDd), 256>>>(p_h2, w_fc11, b_fc11, nullptr, p_a1,
                                    M, HIDd, Cc, 0);
    // 9) fc12 with fused geglu: hid = gelu(a1)*a2 -> reuse g_qkvs as hid buffer
    gemm_cp_k<<<ggrid(HIDd), 256>>>(p_h2, w_fc12, b_fc12, p_a1, p_qkvs,
                                    M, HIDd, Cc, 2);
    // 10) fc2 + y residual -> out
    gemm_cp_k<<<ggrid(Cc), 256>>>(p_qkvs, w_fc2, b_fc2, p_y, out,
                                  M, Cc, HIDd, 3);

    (void)in_sizes; (void)n_in; (void)out_size;
}

// round 8
// speedup vs baseline: 4.0020x; 1.4851x over previous
#include <cuda_runtime.h>
#include <cuda_bf16.h>
#include <math.h>

// ---------------- problem constants ----------------
#define Dd 6
#define Hh 128
#define Ww 128
#define Cc 180
#define NHh 6
#define HDd 30
#define Nn 128
#define NWIN 768
#define NTOK (NWIN * Nn)  // 98304
#define HIDd 360
#define SCALEF 0.18257418583505536f

// ---------------- scratch ----------------
__device__ float g_xw  [NTOK * Cc];
__device__ float g_xwp [NTOK * Cc];
__device__ float g_qkvs[NTOK * 3 * Cc];
__device__ float g_qkvm[NTOK * 3 * Cc];
__device__ float g_xo  [NTOK * 2 * Cc];
__device__ float g_y   [NTOK * Cc];
__device__ float g_h2  [NTOK * Cc];
__device__ float g_a1  [NTOK * HIDd];

__device__ __forceinline__ unsigned smem_u32(const void* p) {
    return (unsigned)__cvta_generic_to_shared(p);
}

#define CP_ASYNC16(saddr, gptr, vb) \
    asm volatile("cp.async.ca.shared.global [%0], [%1], 16, %2;\n" \
                 :: "r"(saddr), "l"(gptr), "r"(vb))

__device__ __forceinline__ void mma_tf32(float* c,
                                         unsigned a0, unsigned a1, unsigned a2, unsigned a3,
                                         unsigned b0, unsigned b1)
{
    asm volatile(
        "mma.sync.aligned.m16n8k8.row.col.f32.tf32.tf32.f32 "
        "{%0,%1,%2,%3}, {%4,%5,%6,%7}, {%8,%9}, {%0,%1,%2,%3};"
        : "+f"(c[0]), "+f"(c[1]), "+f"(c[2]), "+f"(c[3])
        : "r"(a0), "r"(a1), "r"(a2), "r"(a3), "r"(b0), "r"(b1));
}

// ---------------- LN1 + roll + window partition (+pb variant) ----------------
__global__ void ln1_window_k(const float* __restrict__ x,
                             const float* __restrict__ g,
                             const float* __restrict__ b,
                             const float* __restrict__ pb,
                             float* __restrict__ xw,
                             float* __restrict__ xwp)
{
    int warp = (blockIdx.x * blockDim.x + threadIdx.x) >> 5;
    int lane = threadIdx.x & 31;
    if (warp >= NTOK) return;
    int dp = warp / (Hh * Ww);
    int rem = warp % (Hh * Ww);
    int hp = rem >> 7;
    int wp = rem & 127;
    int sd = dp + 1; if (sd >= Dd) sd -= Dd;
    int sh = (hp + 4) & 127;
    int sw = (wp + 4) & 127;
    const float* src = x + ((size_t)(sd * Hh + sh) * Ww + sw) * Cc;

    float vals[6];
    float sum = 0.f, sq = 0.f;
#pragma unroll
    for (int i = 0; i < 6; i++) {
        int c = lane + i * 32;
        float v = (c < Cc) ? src[c] : 0.f;
        vals[i] = v; sum += v; sq += v * v;
    }
#pragma unroll
    for (int o = 16; o; o >>= 1) {
        sum += __shfl_xor_sync(0xffffffffu, sum, o);
        sq  += __shfl_xor_sync(0xffffffffu, sq, o);
    }
    float mean = sum * (1.f / Cc);
    float var  = sq * (1.f / Cc) - mean * mean;
    float rstd = rsqrtf(var + 1e-5f);

    int win = (dp >> 1) * 256 + (hp >> 3) * 16 + (wp >> 3);
    int tok = (dp & 1) * 64 + (hp & 7) * 8 + (wp & 7);
    float* dst  = xw  + (size_t)(win * Nn + tok) * Cc;
    float* dstp = xwp + (size_t)(win * Nn + tok) * Cc;
    const float* prow = pb + (size_t)(tok & 63) * Cc;
#pragma unroll
    for (int i = 0; i < 6; i++) {
        int c = lane + i * 32;
        if (c < Cc) {
            float v = (vals[i] - mean) * rstd * g[c] + b[c];
            dst[c]  = v;
            dstp[c] = v + prow[c];
        }
    }
}

// ---------------- LN2 ----------------
__global__ void ln2_k(const float* __restrict__ y,
                      const float* __restrict__ g,
                      const float* __restrict__ b,
                      float* __restrict__ h2)
{
    int warp = (blockIdx.x * blockDim.x + threadIdx.x) >> 5;
    int lane = threadIdx.x & 31;
    if (warp >= NTOK) return;
    const float* src = y + (size_t)warp * Cc;
    float vals[6];
    float sum = 0.f, sq = 0.f;
#pragma unroll
    for (int i = 0; i < 6; i++) {
        int c = lane + i * 32;
        float v = (c < Cc) ? src[c] : 0.f;
        vals[i] = v; sum += v; sq += v * v;
    }
#pragma unroll
    for (int o = 16; o; o >>= 1) {
        sum += __shfl_xor_sync(0xffffffffu, sum, o);
        sq  += __shfl_xor_sync(0xffffffffu, sq, o);
    }
    float mean = sum * (1.f / Cc);
    float var  = sq * (1.f / Cc) - mean * mean;
    float rstd = rsqrtf(var + 1e-5f);
    float* dst = h2 + (size_t)warp * Cc;
#pragma unroll
    for (int i = 0; i < 6; i++) {
        int c = lane + i * 32;
        if (c < Cc) dst[c] = (vals[i] - mean) * rstd * g[c] + b[c];
    }
}

// ---------------- pipelined TF32 GEMM (cp.async double-buffered) ----------------
#define APITCH 20
#define BPITCH 136

__global__ __launch_bounds__(256, 2)
void gemm_cp_k(const float* __restrict__ A, const float* __restrict__ Bw,
               const float* __restrict__ bias, const float* __restrict__ extra,
               float* __restrict__ Cout, int M, int N, int K, int mode)
{
    __shared__ float As[2][128 * APITCH];
    __shared__ float Bs[2][16 * BPITCH];

    int tid  = threadIdx.x;
    int lane = tid & 31;
    int warp = tid >> 5;
    int wmBase = (warp >> 2) * 64;
    int wnBase = (warp & 3) * 32;
    int g = lane >> 2;
    int t = lane & 3;

    int rowBase = blockIdx.y * 128;
    int colBase = blockIdx.x * 128;

    float acc[4][4][4] = {};

    unsigned asAddr[2] = { smem_u32(&As[0][0]), smem_u32(&As[1][0]) };
    unsigned bsAddr[2] = { smem_u32(&Bs[0][0]), smem_u32(&Bs[1][0]) };

    int nk = (K + 15) >> 4;

    auto loadStage = [&](int s, int k0) {
#pragma unroll
        for (int i = 0; i < 2; i++) {
            int ch = tid + i * 256;
            int r  = ch >> 2;
            int kc = (ch & 3) * 4;
            int gk = k0 + kc;
            bool ok = (gk < K);
            const float* src = ok ? (A + (size_t)(rowBase + r) * K + gk) : A;
            int vb = ok ? 16 : 0;
            CP_ASYNC16(asAddr[s] + (unsigned)(r * APITCH + kc) * 4u, src, vb);
        }
#pragma unroll
        for (int i = 0; i < 2; i++) {
            int ch = tid + i * 256;
            int kr = ch >> 5;
            int nc = (ch & 31) * 4;
            int gk = k0 + kr;
            int gc = colBase + nc;
            bool ok = (gk < K) && (gc < N);
            const float* src = ok ? (Bw + (size_t)gk * N + gc) : Bw;
            int vb = ok ? 16 : 0;
            CP_ASYNC16(bsAddr[s] + (unsigned)(kr * BPITCH + nc) * 4u, src, vb);
        }
    };

    loadStage(0, 0);
    asm volatile("cp.async.commit_group;\n");

    for (int it = 0; it < nk; ++it) {
        if (it + 1 < nk) {
            loadStage((it + 1) & 1, (it + 1) * 16);
            asm volatile("cp.async.commit_group;\n");
            asm volatile("cp.async.wait_group 1;\n");
        } else {
            asm volatile("cp.async.wait_group 0;\n");
        }
        __syncthreads();

        const float* as = As[it & 1];
        const float* bs = Bs[it & 1];
#pragma unroll
        for (int kk = 0; kk < 16; kk += 8) {
            unsigned afr[4][4], bfr[4][2];
#pragma unroll
            for (int mi = 0; mi < 4; mi++) {
                const float* pa = as + (wmBase + mi * 16 + g) * APITCH + kk + t;
                afr[mi][0] = __float_as_uint(pa[0]);
                afr[mi][1] = __float_as_uint(pa[8 * APITCH]);
                afr[mi][2] = __float_as_uint(pa[4]);
                afr[mi][3] = __float_as_uint(pa[8 * APITCH + 4]);
            }
#pragma unroll
            for (int ni = 0; ni < 4; ni++) {
                const float* pbp = bs + (kk + t) * BPITCH + wnBase + ni * 8 + g;
                bfr[ni][0] = __float_as_uint(pbp[0]);
                bfr[ni][1] = __float_as_uint(pbp[4 * BPITCH]);
            }
#pragma unroll
            for (int mi = 0; mi < 4; mi++)
#pragma unroll
                for (int ni = 0; ni < 4; ni++)
                    mma_tf32(acc[mi][ni], afr[mi][0], afr[mi][1], afr[mi][2], afr[mi][3],
                             bfr[ni][0], bfr[ni][1]);
        }
        __syncthreads();
    }

    // ---- epilogue ----
#pragma unroll
    for (int mi = 0; mi < 4; mi++) {
#pragma unroll
        for (int half = 0; half < 2; half++) {
            int gr = rowBase + wmBase + mi * 16 + g + half * 8;
            size_t obase;
            if (mode == 1) {
                int win = gr >> 7, tok = gr & 127;
                int dp  = (win >> 8) * 2 + (tok >> 6);
                int rem = win & 255;
                int hp  = (rem >> 4) * 8 + ((tok >> 3) & 7);
                int wp  = (rem & 15) * 8 + (tok & 7);
                int sd = dp + 1; if (sd >= Dd) sd -= Dd;
                int sh = (hp + 4) & 127;
                int sw = (wp + 4) & 127;
                obase = ((size_t)(sd * Hh + sh) * Ww + sw) * (size_t)Cc;
            } else {
                obase = (size_t)gr * N;
            }
#pragma unroll
            for (int ni = 0; ni < 4; ni++) {
#pragma unroll
                for (int e = 0; e < 2; e++) {
                    int gc = colBase + wnBase + ni * 8 + 2 * t + e;
                    if (gc >= N) continue;
                    float v = acc[mi][ni][half * 2 + e] + bias[gc];
                    if (mode == 1) {
                        v += extra[obase + gc];
                    } else if (mode == 2) {
                        float a = extra[(size_t)gr * N + gc];
                        v *= 0.5f * a * (1.f + erff(a * 0.70710678118654752f));
                    } else if (mode == 3) {
                        v += extra[(size_t)gr * N + gc];
                    }
                    Cout[obase + gc] = v;
                }
            }
        }
    }
}

// ---------------- self-attention via mma (one CTA per win,head) ----------------
// dyn smem (floats): union[16896]{ phaseA: Qs[128*36], Kt[32*132] | phaseB: Ps[128*132] }
//                    Vs[128*36], rpbs[675], rsum2[256], rinv[128]
#define SELF_SMEM_FLOATS (16896 + 4608 + 675 + 256 + 128)

__global__ __launch_bounds__(256, 2)
void attn_self_mma_k(const float* __restrict__ qkv,
                     const float* __restrict__ mask,
                     const float* __restrict__ rpb,
                     const int*   __restrict__ rpi,
                     float* __restrict__ xo)
{
    extern __shared__ float sm[];
    float* Qs    = sm;             // [128][36]
    float* Kt    = sm + 4608;      // [32][132]
    float* Ps    = sm;             // [128][132] (overlays Qs/Kt)
    float* Vs    = sm + 16896;     // [128][36]
    float* rpbs  = Vs + 4608;      // 675
    float* rsum2 = rpbs + 675;     // 256
    float* rinv  = rsum2 + 256;    // 128

    int h   = blockIdx.x;
    int win = blockIdx.y;
    int tid = threadIdx.x, lane = tid & 31, warp = tid >> 5;
    int g = lane >> 2, t = lane & 3;
    const float* base = qkv + (size_t)win * Nn * (3 * Cc);

    for (int i2 = tid; i2 < 128 * 15; i2 += 256) {
        int j = i2 / 15, d2 = i2 - j * 15;
        const float* row = base + j * (3 * Cc) + h * HDd + 2 * d2;
        float2 q = *(const float2*)(row);
        float2 k = *(const float2*)(row + Cc);
        float2 v = *(const float2*)(row + 2 * Cc);
        Qs[j * 36 + 2 * d2]     = q.x * SCALEF;
        Qs[j * 36 + 2 * d2 + 1] = q.y * SCALEF;
        Kt[(2 * d2) * 132 + j]     = k.x;
        Kt[(2 * d2 + 1) * 132 + j] = k.y;
        Vs[j * 36 + 2 * d2]     = v.x;
        Vs[j * 36 + 2 * d2 + 1] = v.y;
    }
    for (int j = tid; j < 128; j += 256) {
        Qs[j * 36 + 30] = 0.f; Qs[j * 36 + 31] = 0.f;
        Vs[j * 36 + 30] = 0.f; Vs[j * 36 + 31] = 0.f;
    }
    for (int i = tid; i < 264; i += 256) Kt[30 * 132 + i] = 0.f;
    for (int i = tid; i < 675; i += 256) rpbs[i] = rpb[i * NHh + h];
    __syncthreads();

    // ---- S = Q @ K^T : warp tile 32x64 (4m x 2n) ----
    int warpM = warp & 3, warpN = warp >> 2;
    float acc[2][8][4] = {};
#pragma unroll
    for (int kk = 0; kk < 32; kk += 8) {
        unsigned afr[2][4], bfr[8][2];
#pragma unroll
        for (int mi = 0; mi < 2; mi++) {
            const float* pa = Qs + (warpM * 32 + mi * 16 + g) * 36 + kk + t;
            afr[mi][0] = __float_as_uint(pa[0]);
            afr[mi][1] = __float_as_uint(pa[8 * 36]);
            afr[mi][2] = __float_as_uint(pa[4]);
            afr[mi][3] = __float_as_uint(pa[8 * 36 + 4]);
        }
#pragma unroll
        for (int ni = 0; ni < 8; ni++) {
            const float* pbp = Kt + (kk + t) * 132 + warpN * 64 + ni * 8 + g;
            bfr[ni][0] = __float_as_uint(pbp[0]);
            bfr[ni][1] = __float_as_uint(pbp[4 * 132]);
        }
#pragma unroll
        for (int mi = 0; mi < 2; mi++)
#pragma unroll
            for (int ni = 0; ni < 8; ni++)
                mma_tf32(acc[mi][ni], afr[mi][0], afr[mi][1], afr[mi][2], afr[mi][3],
                         bfr[ni][0], bfr[ni][1]);
    }
    __syncthreads();   // Qs/Kt dead -> Ps region free

    // ---- bias + mask + exp, rowsum via shfl, store P ----
    const float* mwin = mask + (size_t)win * (Nn * Nn);
#pragma unroll
    for (int mi = 0; mi < 2; mi++) {
#pragma unroll
        for (int half = 0; half < 2; half++) {
            int r = warpM * 32 + mi * 16 + half * 8 + g;
            float s = 0.f;
#pragma unroll
            for (int ni = 0; ni < 8; ni++) {
                int c0 = warpN * 64 + ni * 8 + 2 * t;
                float v0 = acc[mi][ni][half * 2 + 0]
                         + rpbs[__ldg(rpi + r * 128 + c0)]     + __ldg(mwin + r * 128 + c0);
                float v1 = acc[mi][ni][half * 2 + 1]
                         + rpbs[__ldg(rpi + r * 128 + c0 + 1)] + __ldg(mwin + r * 128 + c0 + 1);
                float p0 = __expf(fminf(v0, 60.f));
                float p1 = __expf(fminf(v1, 60.f));
                s += p0 + p1;
                *(float2*)(Ps + r * 132 + c0) = make_float2(p0, p1);
            }
            s += __shfl_xor_sync(0xffffffffu, s, 1);
            s += __shfl_xor_sync(0xffffffffu, s, 2);
            if (t == 0) rsum2[r * 2 + warpN] = s;
        }
    }
    __syncthreads();
    for (int r = tid; r < 128; r += 256) rinv[r] = 1.f / (rsum2[2 * r] + rsum2[2 * r + 1]);
    __syncthreads();

    // ---- O = P @ V : warp tile 16x32 ----
    float oacc[4][4] = {};
    int rb = warp * 16;
#pragma unroll
    for (int kk = 0; kk < 128; kk += 8) {
        const float* pa = Ps + (rb + g) * 132 + kk + t;
        unsigned a0 = __float_as_uint(pa[0]);
        unsigned a1 = __float_as_uint(pa[8 * 132]);
        unsigned a2 = __float_as_uint(pa[4]);
        unsigned a3 = __float_as_uint(pa[8 * 132 + 4]);
        unsigned bfr[4][2];
#pragma unroll
        for (int ni = 0; ni < 4; ni++) {
            const float* pbp = Vs + (kk + t) * 36 + ni * 8 + g;
            bfr[ni][0] = __float_as_uint(pbp[0]);
            bfr[ni][1] = __float_as_uint(pbp[4 * 36]);
        }
#pragma unroll
        for (int ni = 0; ni < 4; ni++)
            mma_tf32(oacc[ni], a0, a1, a2, a3, bfr[ni][0], bfr[ni][1]);
    }
#pragma unroll
    for (int half = 0; half < 2; half++) {
        int r = rb + half * 8 + g;
        float inv = rinv[r];
        float* orow = xo + (size_t)(win * Nn + r) * (2 * Cc) + Cc + h * HDd;
#pragma unroll
        for (int ni = 0; ni < 4; ni++) {
            int d0 = ni * 8 + 2 * t;
            if (d0 < 30)
                *(float2*)(orow + d0) = make_float2(oacc[ni][half * 2 + 0] * inv,
                                                    oacc[ni][half * 2 + 1] * inv);
        }
    }
}

// ---------------- mutual attention via mma (64x64, static smem) ----------------
__global__ __launch_bounds__(128)
void attn_mut_mma_k(const float* __restrict__ qkv,
                    const float* __restrict__ mask,
                    float* __restrict__ xo)
{
    __shared__ float Qs[64 * 36];
    __shared__ float Kt[32 * 68];
    __shared__ float Vs[64 * 36];
    __shared__ float Ps[64 * 68];
    __shared__ float rinv[64];

    int h    = blockIdx.x;
    int win  = blockIdx.y;
    int part = blockIdx.z;
    int tid = threadIdx.x, lane = tid & 31, warp = tid >> 5;
    int g = lane >> 2, t = lane & 3;
    int kvoff = (part == 0) ? 0 : 64;
    int qoff  = (part == 0) ? 64 : 0;
    const float* base = qkv + (size_t)win * Nn * (3 * Cc);

    for (int i2 = tid; i2 < 64 * 15; i2 += 128) {
        int j = i2 / 15, d2 = i2 - j * 15;
        const float* qrow = base + (qoff + j)  * (3 * Cc) + h * HDd + 2 * d2;
        const float* krow = base + (kvoff + j) * (3 * Cc) + h * HDd + 2 * d2;
        float2 q = *(const float2*)(qrow);
        float2 k = *(const float2*)(krow + Cc);
        float2 v = *(const float2*)(krow + 2 * Cc);
        Qs[j * 36 + 2 * d2]     = q.x * SCALEF;
        Qs[j * 36 + 2 * d2 + 1] = q.y * SCALEF;
        Kt[(2 * d2) * 68 + j]     = k.x;
        Kt[(2 * d2 + 1) * 68 + j] = k.y;
        Vs[j * 36 + 2 * d2]     = v.x;
        Vs[j * 36 + 2 * d2 + 1] = v.y;
    }
    for (int j = tid; j < 64; j += 128) {
        Qs[j * 36 + 30] = 0.f; Qs[j * 36 + 31] = 0.f;
        Vs[j * 36 + 30] = 0.f; Vs[j * 36 + 31] = 0.f;
    }
    for (int i = tid; i < 136; i += 128) Kt[30 * 68 + i] = 0.f;
    __syncthreads();

    // ---- S: warp tile 16x64 ----
    int rb = warp * 16;
    float acc[8][4] = {};
#pragma unroll
    for (int kk = 0; kk < 32; kk += 8) {
        const float* pa = Qs + (rb + g) * 36 + kk + t;
        unsigned a0 = __float_as_uint(pa[0]);
        unsigned a1 = __float_as_uint(pa[8 * 36]);
        unsigned a2 = __float_as_uint(pa[4]);
        unsigned a3 = __float_as_uint(pa[8 * 36 + 4]);
        unsigned bfr[8][2];
#pragma unroll
        for (int ni = 0; ni < 8; ni++) {
            const float* pbp = Kt + (kk + t) * 68 + ni * 8 + g;
            bfr[ni][0] = __float_as_uint(pbp[0]);
            bfr[ni][1] = __float_as_uint(pbp[4 * 68]);
        }
#pragma unroll
        for (int ni = 0; ni < 8; ni++)
            mma_tf32(acc[ni], a0, a1, a2, a3, bfr[ni][0], bfr[ni][1]);
    }

    const float* mwin = mask + (size_t)win * (Nn * Nn);
#pragma unroll
    for (int half = 0; half < 2; half++) {
        int r = rb + half * 8 + g;
        float s = 0.f;
#pragma unroll
        for (int ni = 0; ni < 8; ni++) {
            int c0 = ni * 8 + 2 * t;
            float v0 = acc[ni][half * 2 + 0] + __ldg(mwin + r * 128 + c0);
            float v1 = acc[ni][half * 2 + 1] + __ldg(mwin + r * 128 + c0 + 1);
            float p0 = __expf(fminf(v0, 60.f));
            float p1 = __expf(fminf(v1, 60.f));
            s += p0 + p1;
            *(float2*)(Ps + r * 68 + c0) = make_float2(p0, p1);
        }
        s += __shfl_xor_sync(0xffffffffu, s, 1);
        s += __shfl_xor_sync(0xffffffffu, s, 2);
        if (t == 0) rinv[r] = 1.f / s;
    }
    __syncthreads();

    // ---- O = P @ V : warp tile 16x32, k=64 ----
    float oacc[4][4] = {};
#pragma unroll
    for (int kk = 0; kk < 64; kk += 8) {
        const float* pa = Ps + (rb + g) * 68 + kk + t;
        unsigned a0 = __float_as_uint(pa[0]);
        unsigned a1 = __float_as_uint(pa[8 * 68]);
        unsigned a2 = __float_as_uint(pa[4]);
        unsigned a3 = __float_as_uint(pa[8 * 68 + 4]);
        unsigned bfr[4][2];
#pragma unroll
        for (int ni = 0; ni < 4; ni++) {
            const float* pbp = Vs + (kk + t) * 36 + ni * 8 + g;
            bfr[ni][0] = __float_as_uint(pbp[0]);
            bfr[ni][1] = __float_as_uint(pbp[4 * 36]);
        }
#pragma unroll
        for (int ni = 0; ni < 4; ni++)
            mma_tf32(oacc[ni], a0, a1, a2, a3, bfr[ni][0], bfr[ni][1]);
    }
#pragma unroll
    for (int half = 0; half < 2; half++) {
        int r = rb + half * 8 + g;
        float inv = rinv[r];
        float* orow = xo + (size_t)(win * Nn + part * 64 + r) * (2 * Cc) + h * HDd;
#pragma unroll
        for (int ni = 0; ni < 4; ni++) {
            int d0 = ni * 8 + 2 * t;
            if (d0 < 30)
                *(float2*)(orow + d0) = make_float2(oacc[ni][half * 2 + 0] * inv,
                                                    oacc[ni][half * 2 + 1] * inv);
        }
    }
}

// ---------------- launch ----------------
extern "C" void kernel_launch(void* const* d_in, const int* in_sizes, int n_in,
                              void* d_out, int out_size)
{
    const float* x        = (const float*)d_in[0];
    const float* mask     = (const float*)d_in[1];
    const float* g1       = (const float*)d_in[2];
    const float* b1       = (const float*)d_in[3];
    const float* g2       = (const float*)d_in[4];
    const float* b2       = (const float*)d_in[5];
    const float* w_qkv_s  = (const float*)d_in[6];
    const float* b_qkv_s  = (const float*)d_in[7];
    const float* w_qkv_m  = (const float*)d_in[8];
    const float* b_qkv_m  = (const float*)d_in[9];
    const float* rpb      = (const float*)d_in[10];
    const float* pos_bias = (const float*)d_in[11];
    const float* w_proj   = (const float*)d_in[12];
    const float* b_proj   = (const float*)d_in[13];
    const float* w_fc11   = (const float*)d_in[14];
    const float* b_fc11   = (const float*)d_in[15];
    const float* w_fc12   = (const float*)d_in[16];
    const float* b_fc12   = (const float*)d_in[17];
    const float* w_fc2    = (const float*)d_in[18];
    const float* b_fc2    = (const float*)d_in[19];
    const int*   rpi      = (const int*)d_in[20];
    float* out = (float*)d_out;

    float *p_xw, *p_xwp, *p_qkvs, *p_qkvm, *p_xo, *p_y, *p_h2, *p_a1;
    cudaGetSymbolAddress((void**)&p_xw,   g_xw);
    cudaGetSymbolAddress((void**)&p_xwp,  g_xwp);
    cudaGetSymbolAddress((void**)&p_qkvs, g_qkvs);
    cudaGetSymbolAddress((void**)&p_qkvm, g_qkvm);
    cudaGetSymbolAddress((void**)&p_xo,   g_xo);
    cudaGetSymbolAddress((void**)&p_y,    g_y);
    cudaGetSymbolAddress((void**)&p_h2,   g_h2);
    cudaGetSymbolAddress((void**)&p_a1,   g_a1);

    const int M = NTOK;
    auto ggrid = [](int N) { return dim3((unsigned)((N + 127) / 128), NTOK / 128); };

    static int smemSet = 0;
    if (!smemSet) {
        cudaFuncSetAttribute(attn_self_mma_k,
                             cudaFuncAttributeMaxDynamicSharedMemorySize,
                             SELF_SMEM_FLOATS * 4);
        smemSet = 1;
    }

    ln1_window_k<<<(NTOK * 32 + 255) / 256, 256>>>(x, g1, b1, pos_bias, p_xw, p_xwp);

    gemm_cp_k<<<ggrid(3 * Cc), 256>>>(p_xw, w_qkv_s, b_qkv_s, nullptr, p_qkvs,
                                      M, 3 * Cc, Cc, 0);
    gemm_cp_k<<<ggrid(3 * Cc), 256>>>(p_xwp, w_qkv_m, b_qkv_m, nullptr, p_qkvm,
                                      M, 3 * Cc, Cc, 0);

    attn_self_mma_k<<<dim3(NHh, NWIN), 256, SELF_SMEM_FLOATS * 4>>>(
        p_qkvs, mask, rpb, rpi, p_xo);
    attn_mut_mma_k<<<dim3(NHh, NWIN, 2), 128>>>(p_qkvm, mask, p_xo);

    gemm_cp_k<<<ggrid(Cc), 256>>>(p_xo, w_proj, b_proj, x, p_y,
                                  M, Cc, 2 * Cc, 1);
    ln2_k<<<(NTOK * 32 + 255) / 256, 256>>>(p_y, g2, b2, p_h2);
    gemm_cp_k<<<ggrid(HIDd), 256>>>(p_h2, w_fc11, b_fc11, nullptr, p_a1,
                                    M, HIDd, Cc, 0);
    gemm_cp_k<<<ggrid(HIDd), 256>>>(p_h2, w_fc12, b_fc12, p_a1, p_qkvs,
                                    M, HIDd, Cc, 2);
    gemm_cp_k<<<ggrid(Cc), 256>>>(p_qkvs, w_fc2, b_fc2, p_y, out,
                                  M, Cc, HIDd, 3);

    (void)in_sizes; (void)n_in; (void)out_size;
}

// round 9
// speedup vs baseline: 4.2375x; 1.0588x over previous
#include <cuda_runtime.h>
#include <cuda_bf16.h>
#include <math.h>

// ---------------- problem constants ----------------
#define Dd 6
#define Hh 128
#define Ww 128
#define Cc 180
#define NHh 6
#define HDd 30
#define Nn 128
#define NWIN 768
#define NTOK (NWIN * Nn)  // 98304
#define HIDd 360
#define SCALEF 0.18257418583505536f

// ---------------- scratch ----------------
__device__ float g_xw  [NTOK * Cc];
__device__ float g_xwp [NTOK * Cc];
__device__ float g_qkvs[NTOK * 3 * Cc];
__device__ float g_qkvm[NTOK * 3 * Cc];
__device__ float g_xo  [NTOK * 2 * Cc];
__device__ float g_y   [NTOK * Cc];
__device__ float g_h2  [NTOK * Cc];
__device__ float g_a1  [NTOK * HIDd];
__device__ float g_bc  [NHh * Nn * Nn];   // combined rel-pos bias per head

__device__ __forceinline__ unsigned smem_u32(const void* p) {
    return (unsigned)__cvta_generic_to_shared(p);
}

#define CP_ASYNC16(saddr, gptr, vb) \
    asm volatile("cp.async.ca.shared.global [%0], [%1], 16, %2;\n" \
                 :: "r"(saddr), "l"(gptr), "r"(vb))

__device__ __forceinline__ void mma_tf32(float* c,
                                         unsigned a0, unsigned a1, unsigned a2, unsigned a3,
                                         unsigned b0, unsigned b1)
{
    asm volatile(
        "mma.sync.aligned.m16n8k8.row.col.f32.tf32.tf32.f32 "
        "{%0,%1,%2,%3}, {%4,%5,%6,%7}, {%8,%9}, {%0,%1,%2,%3};"
        : "+f"(c[0]), "+f"(c[1]), "+f"(c[2]), "+f"(c[3])
        : "r"(a0), "r"(a1), "r"(a2), "r"(a3), "r"(b0), "r"(b1));
}

// ---------------- combined rel-pos bias ----------------
__global__ void bias_comb_k(const float* __restrict__ rpb,
                            const int*   __restrict__ rpi,
                            float* __restrict__ bc)
{
    int i = blockIdx.x * blockDim.x + threadIdx.x;
    if (i >= NHh * Nn * Nn) return;
    int h  = i / (Nn * Nn);
    int rc = i % (Nn * Nn);
    bc[i] = rpb[rpi[rc] * NHh + h];
}

// ---------------- LN1 + roll + window partition (+pb variant) ----------------
__global__ void ln1_window_k(const float* __restrict__ x,
                             const float* __restrict__ g,
                             const float* __restrict__ b,
                             const float* __restrict__ pb,
                             float* __restrict__ xw,
                             float* __restrict__ xwp)
{
    int warp = (blockIdx.x * blockDim.x + threadIdx.x) >> 5;
    int lane = threadIdx.x & 31;
    if (warp >= NTOK) return;
    int dp = warp / (Hh * Ww);
    int rem = warp % (Hh * Ww);
    int hp = rem >> 7;
    int wp = rem & 127;
    int sd = dp + 1; if (sd >= Dd) sd -= Dd;
    int sh = (hp + 4) & 127;
    int sw = (wp + 4) & 127;
    const float* src = x + ((size_t)(sd * Hh + sh) * Ww + sw) * Cc;

    float vals[6];
    float sum = 0.f, sq = 0.f;
#pragma unroll
    for (int i = 0; i < 6; i++) {
        int c = lane + i * 32;
        float v = (c < Cc) ? src[c] : 0.f;
        vals[i] = v; sum += v; sq += v * v;
    }
#pragma unroll
    for (int o = 16; o; o >>= 1) {
        sum += __shfl_xor_sync(0xffffffffu, sum, o);
        sq  += __shfl_xor_sync(0xffffffffu, sq, o);
    }
    float mean = sum * (1.f / Cc);
    float var  = sq * (1.f / Cc) - mean * mean;
    float rstd = rsqrtf(var + 1e-5f);

    int win = (dp >> 1) * 256 + (hp >> 3) * 16 + (wp >> 3);
    int tok = (dp & 1) * 64 + (hp & 7) * 8 + (wp & 7);
    float* dst  = xw  + (size_t)(win * Nn + tok) * Cc;
    float* dstp = xwp + (size_t)(win * Nn + tok) * Cc;
    const float* prow = pb + (size_t)(tok & 63) * Cc;
#pragma unroll
    for (int i = 0; i < 6; i++) {
        int c = lane + i * 32;
        if (c < Cc) {
            float v = (vals[i] - mean) * rstd * g[c] + b[c];
            dst[c]  = v;
            dstp[c] = v + prow[c];
        }
    }
}

// ---------------- LN2 ----------------
__global__ void ln2_k(const float* __restrict__ y,
                      const float* __restrict__ g,
                      const float* __restrict__ b,
                      float* __restrict__ h2)
{
    int warp = (blockIdx.x * blockDim.x + threadIdx.x) >> 5;
    int lane = threadIdx.x & 31;
    if (warp >= NTOK) return;
    const float* src = y + (size_t)warp * Cc;
    float vals[6];
    float sum = 0.f, sq = 0.f;
#pragma unroll
    for (int i = 0; i < 6; i++) {
        int c = lane + i * 32;
        float v = (c < Cc) ? src[c] : 0.f;
        vals[i] = v; sum += v; sq += v * v;
    }
#pragma unroll
    for (int o = 16; o; o >>= 1) {
        sum += __shfl_xor_sync(0xffffffffu, sum, o);
        sq  += __shfl_xor_sync(0xffffffffu, sq, o);
    }
    float mean = sum * (1.f / Cc);
    float var  = sq * (1.f / Cc) - mean * mean;
    float rstd = rsqrtf(var + 1e-5f);
    float* dst = h2 + (size_t)warp * Cc;
#pragma unroll
    for (int i = 0; i < 6; i++) {
        int c = lane + i * 32;
        if (c < Cc) dst[c] = (vals[i] - mean) * rstd * g[c] + b[c];
    }
}

// ---------------- 4-stage pipelined TF32 GEMM ----------------
#define APITCH 20
#define BPITCH 136
#define ASTAGE (128 * APITCH)
#define BSTAGE (16 * BPITCH)
#define GEMM_SMEM_BYTES ((4 * ASTAGE + 4 * BSTAGE) * 4)

__global__ __launch_bounds__(256, 2)
void gemm_cp_k(const float* __restrict__ A, const float* __restrict__ Bw,
               const float* __restrict__ bias, const float* __restrict__ extra,
               float* __restrict__ Cout, int M, int N, int K, int mode)
{
    extern __shared__ float dsm[];
    float* AsBase = dsm;
    float* BsBase = dsm + 4 * ASTAGE;

    int tid  = threadIdx.x;
    int lane = tid & 31;
    int warp = tid >> 5;
    int wmBase = (warp >> 2) * 64;
    int wnBase = (warp & 3) * 32;
    int g = lane >> 2;
    int t = lane & 3;

    int rowBase = blockIdx.y * 128;
    int colBase = blockIdx.x * 128;

    float acc[4][4][4] = {};

    unsigned asA = smem_u32(AsBase);
    unsigned bsA = smem_u32(BsBase);

    int nk = (K + 15) >> 4;

    auto loadStage = [&](int s, int k0) {
        unsigned aBase = asA + (unsigned)(s * ASTAGE) * 4u;
        unsigned bBase = bsA + (unsigned)(s * BSTAGE) * 4u;
#pragma unroll
        for (int i = 0; i < 2; i++) {
            int ch = tid + i * 256;
            int r  = ch >> 2;
            int kc = (ch & 3) * 4;
            int gk = k0 + kc;
            bool ok = (gk < K);
            const float* src = ok ? (A + (size_t)(rowBase + r) * K + gk) : A;
            int vb = ok ? 16 : 0;
            CP_ASYNC16(aBase + (unsigned)(r * APITCH + kc) * 4u, src, vb);
        }
#pragma unroll
        for (int i = 0; i < 2; i++) {
            int ch = tid + i * 256;
            int kr = ch >> 5;
            int nc = (ch & 31) * 4;
            int gk = k0 + kr;
            int gc = colBase + nc;
            bool ok = (gk < K) && (gc < N);
            const float* src = ok ? (Bw + (size_t)gk * N + gc) : Bw;
            int vb = ok ? 16 : 0;
            CP_ASYNC16(bBase + (unsigned)(kr * BPITCH + nc) * 4u, src, vb);
        }
    };

    int fetch = 0;
#pragma unroll 1
    for (; fetch < 3 && fetch < nk; fetch++) {
        loadStage(fetch & 3, fetch * 16);
        asm volatile("cp.async.commit_group;\n");
    }

#pragma unroll 1
    for (int it = 0; it < nk; ++it) {
        if (fetch < nk) {
            loadStage(fetch & 3, fetch * 16);
            asm volatile("cp.async.commit_group;\n");
            fetch++;
            asm volatile("cp.async.wait_group 3;\n");
        } else {
            asm volatile("cp.async.wait_group 0;\n");
        }
        __syncthreads();

        const float* as = AsBase + (it & 3) * ASTAGE;
        const float* bs = BsBase + (it & 3) * BSTAGE;
#pragma unroll
        for (int kk = 0; kk < 16; kk += 8) {
            unsigned afr[4][4], bfr[4][2];
#pragma unroll
            for (int mi = 0; mi < 4; mi++) {
                const float* pa = as + (wmBase + mi * 16 + g) * APITCH + kk + t;
                afr[mi][0] = __float_as_uint(pa[0]);
                afr[mi][1] = __float_as_uint(pa[8 * APITCH]);
                afr[mi][2] = __float_as_uint(pa[4]);
                afr[mi][3] = __float_as_uint(pa[8 * APITCH + 4]);
            }
#pragma unroll
            for (int ni = 0; ni < 4; ni++) {
                const float* pbp = bs + (kk + t) * BPITCH + wnBase + ni * 8 + g;
                bfr[ni][0] = __float_as_uint(pbp[0]);
                bfr[ni][1] = __float_as_uint(pbp[4 * BPITCH]);
            }
#pragma unroll
            for (int mi = 0; mi < 4; mi++)
#pragma unroll
                for (int ni = 0; ni < 4; ni++)
                    mma_tf32(acc[mi][ni], afr[mi][0], afr[mi][1], afr[mi][2], afr[mi][3],
                             bfr[ni][0], bfr[ni][1]);
        }
        __syncthreads();
    }

    // ---- epilogue ----
#pragma unroll
    for (int mi = 0; mi < 4; mi++) {
#pragma unroll
        for (int half = 0; half < 2; half++) {
            int gr = rowBase + wmBase + mi * 16 + g + half * 8;
            size_t obase;
            if (mode == 1) {
                int win = gr >> 7, tok = gr & 127;
                int dp  = (win >> 8) * 2 + (tok >> 6);
                int rem = win & 255;
                int hp  = (rem >> 4) * 8 + ((tok >> 3) & 7);
                int wp  = (rem & 15) * 8 + (tok & 7);
                int sd = dp + 1; if (sd >= Dd) sd -= Dd;
                int sh = (hp + 4) & 127;
                int sw = (wp + 4) & 127;
                obase = ((size_t)(sd * Hh + sh) * Ww + sw) * (size_t)Cc;
            } else {
                obase = (size_t)gr * N;
            }
#pragma unroll
            for (int ni = 0; ni < 4; ni++) {
#pragma unroll
                for (int e = 0; e < 2; e++) {
                    int gc = colBase + wnBase + ni * 8 + 2 * t + e;
                    if (gc >= N) continue;
                    float v = acc[mi][ni][half * 2 + e] + bias[gc];
                    if (mode == 1) {
                        v += extra[obase + gc];
                    } else if (mode == 2) {
                        float a = extra[(size_t)gr * N + gc];
                        v *= 0.5f * a * (1.f + erff(a * 0.70710678118654752f));
                    } else if (mode == 3) {
                        v += extra[(size_t)gr * N + gc];
                    }
                    Cout[obase + gc] = v;
                }
            }
        }
    }
}

// ---------------- self-attention via mma ----------------
// dyn smem (floats): union[16896]{ Qs[128*36]+Kt[32*132] | Ps[128*132] },
//                    Vs[128*36], rsum2[256], rinv[128]
#define SELF_SMEM_FLOATS (16896 + 4608 + 256 + 128)

__global__ __launch_bounds__(256, 2)
void attn_self_mma_k(const float* __restrict__ qkv,
                     const float* __restrict__ mask,
                     const float* __restrict__ bc,
                     float* __restrict__ xo)
{
    extern __shared__ float sm[];
    float* Qs    = sm;
    float* Kt    = sm + 4608;
    float* Ps    = sm;
    float* Vs    = sm + 16896;
    float* rsum2 = Vs + 4608;
    float* rinv  = rsum2 + 256;

    int h   = blockIdx.x;
    int win = blockIdx.y;
    int tid = threadIdx.x, lane = tid & 31, warp = tid >> 5;
    int g = lane >> 2, t = lane & 3;
    const float* base = qkv + (size_t)win * Nn * (3 * Cc);

    for (int i2 = tid; i2 < 128 * 15; i2 += 256) {
        int j = i2 / 15, d2 = i2 - j * 15;
        const float* row = base + j * (3 * Cc) + h * HDd + 2 * d2;
        float2 q = *(const float2*)(row);
        float2 k = *(const float2*)(row + Cc);
        float2 v = *(const float2*)(row + 2 * Cc);
        Qs[j * 36 + 2 * d2]     = q.x * SCALEF;
        Qs[j * 36 + 2 * d2 + 1] = q.y * SCALEF;
        Kt[(2 * d2) * 132 + j]     = k.x;
        Kt[(2 * d2 + 1) * 132 + j] = k.y;
        Vs[j * 36 + 2 * d2]     = v.x;
        Vs[j * 36 + 2 * d2 + 1] = v.y;
    }
    for (int j = tid; j < 128; j += 256) {
        Qs[j * 36 + 30] = 0.f; Qs[j * 36 + 31] = 0.f;
        Vs[j * 36 + 30] = 0.f; Vs[j * 36 + 31] = 0.f;
    }
    for (int i = tid; i < 264; i += 256) Kt[30 * 132 + i] = 0.f;
    __syncthreads();

    // ---- S = Q @ K^T ----
    int warpM = warp & 3, warpN = warp >> 2;
    float acc[2][8][4] = {};
#pragma unroll
    for (int kk = 0; kk < 32; kk += 8) {
        unsigned afr[2][4], bfr[8][2];
#pragma unroll
        for (int mi = 0; mi < 2; mi++) {
            const float* pa = Qs + (warpM * 32 + mi * 16 + g) * 36 + kk + t;
            afr[mi][0] = __float_as_uint(pa[0]);
            afr[mi][1] = __float_as_uint(pa[8 * 36]);
            afr[mi][2] = __float_as_uint(pa[4]);
            afr[mi][3] = __float_as_uint(pa[8 * 36 + 4]);
        }
#pragma unroll
        for (int ni = 0; ni < 8; ni++) {
            const float* pbp = Kt + (kk + t) * 132 + warpN * 64 + ni * 8 + g;
            bfr[ni][0] = __float_as_uint(pbp[0]);
            bfr[ni][1] = __float_as_uint(pbp[4 * 132]);
        }
#pragma unroll
        for (int mi = 0; mi < 2; mi++)
#pragma unroll
            for (int ni = 0; ni < 8; ni++)
                mma_tf32(acc[mi][ni], afr[mi][0], afr[mi][1], afr[mi][2], afr[mi][3],
                         bfr[ni][0], bfr[ni][1]);
    }
    __syncthreads();

    // ---- bias + mask + exp, rowsum, store P ----
    const float* mwin = mask + (size_t)win * (Nn * Nn);
    const float* bch  = bc + (size_t)h * (Nn * Nn);
#pragma unroll
    for (int mi = 0; mi < 2; mi++) {
#pragma unroll
        for (int half = 0; half < 2; half++) {
            int r = warpM * 32 + mi * 16 + half * 8 + g;
            float s = 0.f;
#pragma unroll
            for (int ni = 0; ni < 8; ni++) {
                int c0 = warpN * 64 + ni * 8 + 2 * t;
                float2 b2 = *(const float2*)(bch + r * 128 + c0);
                float2 m2 = *(const float2*)(mwin + r * 128 + c0);
                float p0 = __expf(fminf(acc[mi][ni][half * 2 + 0] + b2.x + m2.x, 60.f));
                float p1 = __expf(fminf(acc[mi][ni][half * 2 + 1] + b2.y + m2.y, 60.f));
                s += p0 + p1;
                *(float2*)(Ps + r * 132 + c0) = make_float2(p0, p1);
            }
            s += __shfl_xor_sync(0xffffffffu, s, 1);
            s += __shfl_xor_sync(0xffffffffu, s, 2);
            if (t == 0) rsum2[r * 2 + warpN] = s;
        }
    }
    __syncthreads();
    for (int r = tid; r < 128; r += 256) rinv[r] = 1.f / (rsum2[2 * r] + rsum2[2 * r + 1]);
    __syncthreads();

    // ---- O = P @ V ----
    float oacc[4][4] = {};
    int rb = warp * 16;
#pragma unroll
    for (int kk = 0; kk < 128; kk += 8) {
        const float* pa = Ps + (rb + g) * 132 + kk + t;
        unsigned a0 = __float_as_uint(pa[0]);
        unsigned a1 = __float_as_uint(pa[8 * 132]);
        unsigned a2 = __float_as_uint(pa[4]);
        unsigned a3 = __float_as_uint(pa[8 * 132 + 4]);
        unsigned bfr[4][2];
#pragma unroll
        for (int ni = 0; ni < 4; ni++) {
            const float* pbp = Vs + (kk + t) * 36 + ni * 8 + g;
            bfr[ni][0] = __float_as_uint(pbp[0]);
            bfr[ni][1] = __float_as_uint(pbp[4 * 36]);
        }
#pragma unroll
        for (int ni = 0; ni < 4; ni++)
            mma_tf32(oacc[ni], a0, a1, a2, a3, bfr[ni][0], bfr[ni][1]);
    }
#pragma unroll
    for (int half = 0; half < 2; half++) {
        int r = rb + half * 8 + g;
        float inv = rinv[r];
        float* orow = xo + (size_t)(win * Nn + r) * (2 * Cc) + Cc + h * HDd;
#pragma unroll
        for (int ni = 0; ni < 4; ni++) {
            int d0 = ni * 8 + 2 * t;
            if (d0 < 30)
                *(float2*)(orow + d0) = make_float2(oacc[ni][half * 2 + 0] * inv,
                                                    oacc[ni][half * 2 + 1] * inv);
        }
    }
}

// ---------------- mutual attention via mma (64x64) ----------------
__global__ __launch_bounds__(128)
void attn_mut_mma_k(const float* __restrict__ qkv,
                    const float* __restrict__ mask,
                    float* __restrict__ xo)
{
    __shared__ float Qs[64 * 36];
    __shared__ float Kt[32 * 68];
    __shared__ float Vs[64 * 36];
    __shared__ float Ps[64 * 68];
    __shared__ float rinv[64];

    int h    = blockIdx.x;
    int win  = blockIdx.y;
    int part = blockIdx.z;
    int tid = threadIdx.x, lane = tid & 31, warp = tid >> 5;
    int g = lane >> 2, t = lane & 3;
    int kvoff = (part == 0) ? 0 : 64;
    int qoff  = (part == 0) ? 64 : 0;
    const float* base = qkv + (size_t)win * Nn * (3 * Cc);

    for (int i2 = tid; i2 < 64 * 15; i2 += 128) {
        int j = i2 / 15, d2 = i2 - j * 15;
        const float* qrow = base + (qoff + j)  * (3 * Cc) + h * HDd + 2 * d2;
        const float* krow = base + (kvoff + j) * (3 * Cc) + h * HDd + 2 * d2;
        float2 q = *(const float2*)(qrow);
        float2 k = *(const float2*)(krow + Cc);
        float2 v = *(const float2*)(krow + 2 * Cc);
        Qs[j * 36 + 2 * d2]     = q.x * SCALEF;
        Qs[j * 36 + 2 * d2 + 1] = q.y * SCALEF;
        Kt[(2 * d2) * 68 + j]     = k.x;
        Kt[(2 * d2 + 1) * 68 + j] = k.y;
        Vs[j * 36 + 2 * d2]     = v.x;
        Vs[j * 36 + 2 * d2 + 1] = v.y;
    }
    for (int j = tid; j < 64; j += 128) {
        Qs[j * 36 + 30] = 0.f; Qs[j * 36 + 31] = 0.f;
        Vs[j * 36 + 30] = 0.f; Vs[j * 36 + 31] = 0.f;
    }
    for (int i = tid; i < 136; i += 128) Kt[30 * 68 + i] = 0.f;
    __syncthreads();

    int rb = warp * 16;
    float acc[8][4] = {};
#pragma unroll
    for (int kk = 0; kk < 32; kk += 8) {
        const float* pa = Qs + (rb + g) * 36 + kk + t;
        unsigned a0 = __float_as_uint(pa[0]);
        unsigned a1 = __float_as_uint(pa[8 * 36]);
        unsigned a2 = __float_as_uint(pa[4]);
        unsigned a3 = __float_as_uint(pa[8 * 36 + 4]);
        unsigned bfr[8][2];
#pragma unroll
        for (int ni = 0; ni < 8; ni++) {
            const float* pbp = Kt + (kk + t) * 68 + ni * 8 + g;
            bfr[ni][0] = __float_as_uint(pbp[0]);
            bfr[ni][1] = __float_as_uint(pbp[4 * 68]);
        }
#pragma unroll
        for (int ni = 0; ni < 8; ni++)
            mma_tf32(acc[ni], a0, a1, a2, a3, bfr[ni][0], bfr[ni][1]);
    }

    const float* mwin = mask + (size_t)win * (Nn * Nn);
#pragma unroll
    for (int half = 0; half < 2; half++) {
        int r = rb + half * 8 + g;
        float s = 0.f;
#pragma unroll
        for (int ni = 0; ni < 8; ni++) {
            int c0 = ni * 8 + 2 * t;
            float2 m2 = *(const float2*)(mwin + r * 128 + c0);
            float p0 = __expf(fminf(acc[ni][half * 2 + 0] + m2.x, 60.f));
            float p1 = __expf(fminf(acc[ni][half * 2 + 1] + m2.y, 60.f));
            s += p0 + p1;
            *(float2*)(Ps + r * 68 + c0) = make_float2(p0, p1);
        }
        s += __shfl_xor_sync(0xffffffffu, s, 1);
        s += __shfl_xor_sync(0xffffffffu, s, 2);
        if (t == 0) rinv[r] = 1.f / s;
    }
    __syncthreads();

    float oacc[4][4] = {};
#pragma unroll
    for (int kk = 0; kk < 64; kk += 8) {
        const float* pa = Ps + (rb + g) * 68 + kk + t;
        unsigned a0 = __float_as_uint(pa[0]);
        unsigned a1 = __float_as_uint(pa[8 * 68]);
        unsigned a2 = __float_as_uint(pa[4]);
        unsigned a3 = __float_as_uint(pa[8 * 68 + 4]);
        unsigned bfr[4][2];
#pragma unroll
        for (int ni = 0; ni < 4; ni++) {
            const float* pbp = Vs + (kk + t) * 36 + ni * 8 + g;
            bfr[ni][0] = __float_as_uint(pbp[0]);
            bfr[ni][1] = __float_as_uint(pbp[4 * 36]);
        }
#pragma unroll
        for (int ni = 0; ni < 4; ni++)
            mma_tf32(oacc[ni], a0, a1, a2, a3, bfr[ni][0], bfr[ni][1]);
    }
#pragma unroll
    for (int half = 0; half < 2; half++) {
        int r = rb + half * 8 + g;
        float inv = rinv[r];
        float* orow = xo + (size_t)(win * Nn + part * 64 + r) * (2 * Cc) + h * HDd;
#pragma unroll
        for (int ni = 0; ni < 4; ni++) {
            int d0 = ni * 8 + 2 * t;
            if (d0 < 30)
                *(float2*)(orow + d0) = make_float2(oacc[ni][half * 2 + 0] * inv,
                                                    oacc[ni][half * 2 + 1] * inv);
        }
    }
}

// ---------------- launch ----------------
extern "C" void kernel_launch(void* const* d_in, const int* in_sizes, int n_in,
                              void* d_out, int out_size)
{
    const float* x        = (const float*)d_in[0];
    const float* mask     = (const float*)d_in[1];
    const float* g1       = (const float*)d_in[2];
    const float* b1       = (const float*)d_in[3];
    const float* g2       = (const float*)d_in[4];
    const float* b2       = (const float*)d_in[5];
    const float* w_qkv_s  = (const float*)d_in[6];
    const float* b_qkv_s  = (const float*)d_in[7];
    const float* w_qkv_m  = (const float*)d_in[8];
    const float* b_qkv_m  = (const float*)d_in[9];
    const float* rpb      = (const float*)d_in[10];
    const float* pos_bias = (const float*)d_in[11];
    const float* w_proj   = (const float*)d_in[12];
    const float* b_proj   = (const float*)d_in[13];
    const float* w_fc11   = (const float*)d_in[14];
    const float* b_fc11   = (const float*)d_in[15];
    const float* w_fc12   = (const float*)d_in[16];
    const float* b_fc12   = (const float*)d_in[17];
    const float* w_fc2    = (const float*)d_in[18];
    const float* b_fc2    = (const float*)d_in[19];
    const int*   rpi      = (const int*)d_in[20];
    float* out = (float*)d_out;

    float *p_xw, *p_xwp, *p_qkvs, *p_qkvm, *p_xo, *p_y, *p_h2, *p_a1, *p_bc;
    cudaGetSymbolAddress((void**)&p_xw,   g_xw);
    cudaGetSymbolAddress((void**)&p_xwp,  g_xwp);
    cudaGetSymbolAddress((void**)&p_qkvs, g_qkvs);
    cudaGetSymbolAddress((void**)&p_qkvm, g_qkvm);
    cudaGetSymbolAddress((void**)&p_xo,   g_xo);
    cudaGetSymbolAddress((void**)&p_y,    g_y);
    cudaGetSymbolAddress((void**)&p_h2,   g_h2);
    cudaGetSymbolAddress((void**)&p_a1,   g_a1);
    cudaGetSymbolAddress((void**)&p_bc,   g_bc);

    const int M = NTOK;
    auto ggrid = [](int N) { return dim3((unsigned)((N + 127) / 128), NTOK / 128); };

    static int attrSet = 0;
    if (!attrSet) {
        cudaFuncSetAttribute(attn_self_mma_k,
                             cudaFuncAttributeMaxDynamicSharedMemorySize,
                             SELF_SMEM_FLOATS * 4);
        cudaFuncSetAttribute(gemm_cp_k,
                             cudaFuncAttributeMaxDynamicSharedMemorySize,
                             GEMM_SMEM_BYTES);
        attrSet = 1;
    }

    bias_comb_k<<<(NHh * Nn * Nn + 255) / 256, 256>>>(rpb, rpi, p_bc);
    ln1_window_k<<<(NTOK * 32 + 255) / 256, 256>>>(x, g1, b1, pos_bias, p_xw, p_xwp);

    gemm_cp_k<<<ggrid(3 * Cc), 256, GEMM_SMEM_BYTES>>>(
        p_xw, w_qkv_s, b_qkv_s, nullptr, p_qkvs, M, 3 * Cc, Cc, 0);
    gemm_cp_k<<<ggrid(3 * Cc), 256, GEMM_SMEM_BYTES>>>(
        p_xwp, w_qkv_m, b_qkv_m, nullptr, p_qkvm, M, 3 * Cc, Cc, 0);

    attn_self_mma_k<<<dim3(NHh, NWIN), 256, SELF_SMEM_FLOATS * 4>>>(
        p_qkvs, mask, p_bc, p_xo);
    attn_mut_mma_k<<<dim3(NHh, NWIN, 2), 128>>>(p_qkvm, mask, p_xo);

    gemm_cp_k<<<ggrid(Cc), 256, GEMM_SMEM_BYTES>>>(
        p_xo, w_proj, b_proj, x, p_y, M, Cc, 2 * Cc, 1);
    ln2_k<<<(NTOK * 32 + 255) / 256, 256>>>(p_y, g2, b2, p_h2);
    gemm_cp_k<<<ggrid(HIDd), 256, GEMM_SMEM_BYTES>>>(
        p_h2, w_fc11, b_fc11, nullptr, p_a1, M, HIDd, Cc, 0);
    gemm_cp_k<<<ggrid(HIDd), 256, GEMM_SMEM_BYTES>>>(
        p_h2, w_fc12, b_fc12, p_a1, p_qkvs, M, HIDd, Cc, 2);
    gemm_cp_k<<<ggrid(Cc), 256, GEMM_SMEM_BYTES>>>(
        p_qkvs, w_fc2, b_fc2, p_y, out, M, Cc, HIDd, 3);

    (void)in_sizes; (void)n_in; (void)out_size;
}

// round 13
// speedup vs baseline: 5.2753x; 1.2449x over previous
#include <cuda_runtime.h>
#include <cuda_fp16.h>
#include <math.h>

// ---------------- problem constants ----------------
#define Dd 6
#define Hh 128
#define Ww 128
#define Cc 180
#define NHh 6
#define HDd 30
#define Nn 128
#define NWIN 768
#define NTOK (NWIN * Nn)  // 98304
#define HIDd 360
#define SCALEF 0.18257418583505536f
#define KP1 192   // padded K for K=180
#define KP2 384   // padded K for K=360

// ---------------- scratch ----------------
__device__ __half g_xw_h [NTOK * KP1];
__device__ __half g_xwp_h[NTOK * KP1];
__device__ float  g_qkvs [NTOK * 3 * Cc];
__device__ float  g_qkvm [NTOK * 3 * Cc];
__device__ __half g_xo_h [NTOK * KP2];
__device__ float  g_y    [NTOK * Cc];
__device__ __half g_h2_h [NTOK * KP1];
__device__ float  g_a1   [NTOK * HIDd];
__device__ __half g_hid_h[NTOK * KP2];
__device__ float  g_bc   [NHh * Nn * Nn];
// transposed half weights [N][Kp]
__device__ __half g_wqkvs_t[540 * KP1];
__device__ __half g_wqkvm_t[540 * KP1];
__device__ __half g_wproj_t[180 * KP2];
__device__ __half g_wfc11_t[360 * KP1];
__device__ __half g_wfc12_t[360 * KP1];
__device__ __half g_wfc2_t [180 * KP2];

__device__ __forceinline__ unsigned smem_u32(const void* p) {
    return (unsigned)__cvta_generic_to_shared(p);
}

#define CP_ASYNC16(saddr, gptr, vb) \
    asm volatile("cp.async.ca.shared.global [%0], [%1], 16, %2;\n" \
                 :: "r"(saddr), "l"(gptr), "r"(vb))

__device__ __forceinline__ void mma_tf32(float* c,
                                         unsigned a0, unsigned a1, unsigned a2, unsigned a3,
                                         unsigned b0, unsigned b1)
{
    asm volatile(
        "mma.sync.aligned.m16n8k8.row.col.f32.tf32.tf32.f32 "
        "{%0,%1,%2,%3}, {%4,%5,%6,%7}, {%8,%9}, {%0,%1,%2,%3};"
        : "+f"(c[0]), "+f"(c[1]), "+f"(c[2]), "+f"(c[3])
        : "r"(a0), "r"(a1), "r"(a2), "r"(a3), "r"(b0), "r"(b1));
}

__device__ __forceinline__ void mma_f16(float* c,
                                        unsigned a0, unsigned a1, unsigned a2, unsigned a3,
                                        unsigned b0, unsigned b1)
{
    asm volatile(
        "mma.sync.aligned.m16n8k16.row.col.f32.f16.f16.f32 "
        "{%0,%1,%2,%3}, {%4,%5,%6,%7}, {%8,%9}, {%0,%1,%2,%3};"
        : "+f"(c[0]), "+f"(c[1]), "+f"(c[2]), "+f"(c[3])
        : "r"(a0), "r"(a1), "r"(a2), "r"(a3), "r"(b0), "r"(b1));
}

// ---------------- weight convert + transpose: dst[n][k] = src[k][n] ----------------
__global__ void wconv_k(const float* __restrict__ src, __half* __restrict__ dst,
                        int K, int N, int Kp)
{
    int i = blockIdx.x * blockDim.x + threadIdx.x;
    if (i >= N * Kp) return;
    int n = i / Kp, k = i - n * Kp;
    dst[i] = (k < K) ? __float2half_rn(src[(size_t)k * N + n]) : __half(0.f);
}

// ---------------- zero activation pads ----------------
__global__ void pad_k()
{
    int i = blockIdx.x * blockDim.x + threadIdx.x;
    if (i >= NTOK * 84) return;
    int t = i / 84, j = i - t * 84;
    if (j < 12)       g_xw_h [(size_t)t * KP1 + 180 + j]        = __half(0.f);
    else if (j < 24)  g_xwp_h[(size_t)t * KP1 + 180 + (j - 12)] = __half(0.f);
    else if (j < 36)  g_h2_h [(size_t)t * KP1 + 180 + (j - 24)] = __half(0.f);
    else if (j < 60)  g_xo_h [(size_t)t * KP2 + 360 + (j - 36)] = __half(0.f);
    else              g_hid_h[(size_t)t * KP2 + 360 + (j - 60)] = __half(0.f);
}

// ---------------- combined rel-pos bias ----------------
__global__ void bias_comb_k(const float* __restrict__ rpb,
                            const int*   __restrict__ rpi,
                            float* __restrict__ bc)
{
    int i = blockIdx.x * blockDim.x + threadIdx.x;
    if (i >= NHh * Nn * Nn) return;
    int h  = i / (Nn * Nn);
    int rc = i % (Nn * Nn);
    bc[i] = rpb[rpi[rc] * NHh + h];
}

// ---------------- LN1 + roll + window partition (half out) ----------------
__global__ void ln1_window_k(const float* __restrict__ x,
                             const float* __restrict__ g,
                             const float* __restrict__ b,
                             const float* __restrict__ pb,
                             __half* __restrict__ xw,
                             __half* __restrict__ xwp)
{
    int warp = (blockIdx.x * blockDim.x + threadIdx.x) >> 5;
    int lane = threadIdx.x & 31;
    if (warp >= NTOK) return;
    int dp = warp / (Hh * Ww);
    int rem = warp % (Hh * Ww);
    int hp = rem >> 7;
    int wp = rem & 127;
    int sd = dp + 1; if (sd >= Dd) sd -= Dd;
    int sh = (hp + 4) & 127;
    int sw = (wp + 4) & 127;
    const float* src = x + ((size_t)(sd * Hh + sh) * Ww + sw) * Cc;

    float vals[6];
    float sum = 0.f, sq = 0.f;
#pragma unroll
    for (int i = 0; i < 6; i++) {
        int c = lane + i * 32;
        float v = (c < Cc) ? src[c] : 0.f;
        vals[i] = v; sum += v; sq += v * v;
    }
#pragma unroll
    for (int o = 16; o; o >>= 1) {
        sum += __shfl_xor_sync(0xffffffffu, sum, o);
        sq  += __shfl_xor_sync(0xffffffffu, sq, o);
    }
    float mean = sum * (1.f / Cc);
    float var  = sq * (1.f / Cc) - mean * mean;
    float rstd = rsqrtf(var + 1e-5f);

    int win = (dp >> 1) * 256 + (hp >> 3) * 16 + (wp >> 3);
    int tok = (dp & 1) * 64 + (hp & 7) * 8 + (wp & 7);
    __half* dst  = xw  + (size_t)(win * Nn + tok) * KP1;
    __half* dstp = xwp + (size_t)(win * Nn + tok) * KP1;
    const float* prow = pb + (size_t)(tok & 63) * Cc;
#pragma unroll
    for (int i = 0; i < 6; i++) {
        int c = lane + i * 32;
        if (c < Cc) {
            float v = (vals[i] - mean) * rstd * g[c] + b[c];
            dst[c]  = __float2half_rn(v);
            dstp[c] = __float2half_rn(v + prow[c]);
        }
    }
}

// ---------------- LN2: y (fp32, pitch Cc) -> h2 (half, pitch KP1) ----------------
__global__ void ln2_k(const float* __restrict__ y,
                      const float* __restrict__ g,
                      const float* __restrict__ b,
                      __half* __restrict__ h2)
{
    int warp = (blockIdx.x * blockDim.x + threadIdx.x) >> 5;
    int lane = threadIdx.x & 31;
    if (warp >= NTOK) return;
    const float* src = y + (size_t)warp * Cc;
    float vals[6];
    float sum = 0.f, sq = 0.f;
#pragma unroll
    for (int i = 0; i < 6; i++) {
        int c = lane + i * 32;
        float v = (c < Cc) ? src[c] : 0.f;
        vals[i] = v; sum += v; sq += v * v;
    }
#pragma unroll
    for (int o = 16; o; o >>= 1) {
        sum += __shfl_xor_sync(0xffffffffu, sum, o);
        sq  += __shfl_xor_sync(0xffffffffu, sq, o);
    }
    float mean = sum * (1.f / Cc);
    float var  = sq * (1.f / Cc) - mean * mean;
    float rstd = rsqrtf(var + 1e-5f);
    __half* dst = h2 + (size_t)warp * KP1;
#pragma unroll
    for (int i = 0; i < 6; i++) {
        int c = lane + i * 32;
        if (c < Cc) dst[c] = __float2half_rn((vals[i] - mean) * rstd * g[c] + b[c]);
    }
}

// ---------------- fp16 4-stage pipelined GEMM ----------------
// A[M][Kp] half, B[N][Kp] half (transposed weights). C = A@B^T + bias.
// modes: 0 fp32 out; 1 scatter+x-resid fp32; 2 geglu half out; 3 resid fp32.
#define HP 40                 // smem pitch (halves) for A and B tiles
#define HSTAGE (128 * HP)     // halves per stage per matrix
#define GEMM_SMEM_BYTES (4 * 2 * HSTAGE * 2)   // 81920

__global__ __launch_bounds__(256, 2)
void gemm_h_k(const __half* __restrict__ A, const __half* __restrict__ Bw,
              const float* __restrict__ bias, const float* __restrict__ extra,
              void* __restrict__ Cout, int M, int N, int Kp, int cpitch, int mode)
{
    extern __shared__ __half hsm[];
    __half* AsBase = hsm;
    __half* BsBase = hsm + 4 * HSTAGE;

    int tid  = threadIdx.x;
    int lane = tid & 31;
    int warp = tid >> 5;
    int wmBase = (warp >> 2) * 64;
    int wnBase = (warp & 3) * 32;
    int g = lane >> 2;
    int t = lane & 3;

    int rowBase = blockIdx.y * 128;
    int colBase = blockIdx.x * 128;

    float acc[4][4][4] = {};

    unsigned asA = smem_u32(AsBase);
    unsigned bsA = smem_u32(BsBase);

    int nk = Kp >> 5;

    auto loadStage = [&](int s, int k0) {
        unsigned aB = asA + (unsigned)(s * HSTAGE) * 2u;
        unsigned bB = bsA + (unsigned)(s * HSTAGE) * 2u;
#pragma unroll
        for (int i = 0; i < 2; i++) {
            int ch = tid + i * 256;
            int r  = ch >> 2;
            int kc = (ch & 3) * 8;          // halves
            const __half* src = A + (size_t)(rowBase + r) * Kp + k0 + kc;
            CP_ASYNC16(aB + (unsigned)(r * HP + kc) * 2u, src, 16);
        }
#pragma unroll
        for (int i = 0; i < 2; i++) {
            int ch = tid + i * 256;
            int r  = ch >> 2;
            int kc = (ch & 3) * 8;
            bool ok = (colBase + r) < N;
            const __half* src = ok ? (Bw + (size_t)(colBase + r) * Kp + k0 + kc) : Bw;
            int vb = ok ? 16 : 0;
            CP_ASYNC16(bB + (unsigned)(r * HP + kc) * 2u, src, vb);
        }
    };

    int fetch = 0;
#pragma unroll 1
    for (; fetch < 3 && fetch < nk; fetch++) {
        loadStage(fetch & 3, fetch * 32);
        asm volatile("cp.async.commit_group;\n");
    }

#pragma unroll 1
    for (int it = 0; it < nk; ++it) {
        if (fetch < nk) {
            loadStage(fetch & 3, fetch * 32);
            asm volatile("cp.async.commit_group;\n");
            fetch++;
            asm volatile("cp.async.wait_group 3;\n");
        } else {
            asm volatile("cp.async.wait_group 0;\n");
        }
        __syncthreads();

        const __half* as = AsBase + (it & 3) * HSTAGE;
        const __half* bs = BsBase + (it & 3) * HSTAGE;
#pragma unroll
        for (int kk = 0; kk < 32; kk += 16) {
            unsigned afr[4][4], bfr[4][2];
#pragma unroll
            for (int mi = 0; mi < 4; mi++) {
                const __half* pa = as + (wmBase + mi * 16 + g) * HP + kk + 2 * t;
                afr[mi][0] = *(const unsigned*)(pa);
                afr[mi][1] = *(const unsigned*)(pa + 8 * HP);
                afr[mi][2] = *(const unsigned*)(pa + 8);
                afr[mi][3] = *(const unsigned*)(pa + 8 * HP + 8);
            }
#pragma unroll
            for (int ni = 0; ni < 4; ni++) {
                const __half* pbp = bs + (wnBase + ni * 8 + g) * HP + kk + 2 * t;
                bfr[ni][0] = *(const unsigned*)(pbp);
                bfr[ni][1] = *(const unsigned*)(pbp + 8);
            }
#pragma unroll
            for (int mi = 0; mi < 4; mi++)
#pragma unroll
                for (int ni = 0; ni < 4; ni++)
                    mma_f16(acc[mi][ni], afr[mi][0], afr[mi][1], afr[mi][2], afr[mi][3],
                            bfr[ni][0], bfr[ni][1]);
        }
        __syncthreads();
    }

    // ---- epilogue ----
#pragma unroll
    for (int mi = 0; mi < 4; mi++) {
#pragma unroll
        for (int hf = 0; hf < 2; hf++) {
            int gr = rowBase + wmBase + mi * 16 + g + hf * 8;
            size_t obase;
            if (mode == 1) {
                int win = gr >> 7, tok = gr & 127;
                int dp  = (win >> 8) * 2 + (tok >> 6);
                int rem = win & 255;
                int hp  = (rem >> 4) * 8 + ((tok >> 3) & 7);
                int wp  = (rem & 15) * 8 + (tok & 7);
                int sd = dp + 1; if (sd >= Dd) sd -= Dd;
                int sh = (hp + 4) & 127;
                int sw = (wp + 4) & 127;
                obase = ((size_t)(sd * Hh + sh) * Ww + sw) * (size_t)Cc;
            } else {
                obase = (size_t)gr * cpitch;
            }
#pragma unroll
            for (int ni = 0; ni < 4; ni++) {
#pragma unroll
                for (int e = 0; e < 2; e++) {
                    int gc = colBase + wnBase + ni * 8 + 2 * t + e;
                    if (gc >= N) continue;
                    float v = acc[mi][ni][hf * 2 + e] + bias[gc];
                    if (mode == 1) {
                        v += extra[obase + gc];
                        ((float*)Cout)[obase + gc] = v;
                    } else if (mode == 2) {
                        float a = extra[(size_t)gr * N + gc];
                        v *= 0.5f * a * (1.f + erff(a * 0.70710678118654752f));
                        ((__half*)Cout)[obase + gc] = __float2half_rn(v);
                    } else if (mode == 3) {
                        v += extra[(size_t)gr * N + gc];
                        ((float*)Cout)[obase + gc] = v;
                    } else {
                        ((float*)Cout)[obase + gc] = v;
                    }
                }
            }
        }
    }
}

// ---------------- self-attention via tf32 mma ----------------
#define SELF_SMEM_FLOATS (16896 + 4608 + 256 + 128)

__global__ __launch_bounds__(256, 2)
void attn_self_mma_k(const float* __restrict__ qkv,
                     const float* __restrict__ mask,
                     const float* __restrict__ bc,
                     __half* __restrict__ xo)
{
    extern __shared__ float sm[];
    float* Qs    = sm;
    float* Kt    = sm + 4608;
    float* Ps    = sm;
    float* Vs    = sm + 16896;
    float* rsum2 = Vs + 4608;
    float* rinv  = rsum2 + 256;

    int h   = blockIdx.x;
    int win = blockIdx.y;
    int tid = threadIdx.x, lane = tid & 31, warp = tid >> 5;
    int g = lane >> 2, t = lane & 3;
    const float* base = qkv + (size_t)win * Nn * (3 * Cc);

    for (int i2 = tid; i2 < 128 * 15; i2 += 256) {
        int j = i2 / 15, d2 = i2 - j * 15;
        const float* row = base + j * (3 * Cc) + h * HDd + 2 * d2;
        float2 q = *(const float2*)(row);
        float2 k = *(const float2*)(row + Cc);
        float2 v = *(const float2*)(row + 2 * Cc);
        Qs[j * 36 + 2 * d2]     = q.x * SCALEF;
        Qs[j * 36 + 2 * d2 + 1] = q.y * SCALEF;
        Kt[(2 * d2) * 132 + j]     = k.x;
        Kt[(2 * d2 + 1) * 132 + j] = k.y;
        Vs[j * 36 + 2 * d2]     = v.x;
        Vs[j * 36 + 2 * d2 + 1] = v.y;
    }
    for (int j = tid; j < 128; j += 256) {
        Qs[j * 36 + 30] = 0.f; Qs[j * 36 + 31] = 0.f;
        Vs[j * 36 + 30] = 0.f; Vs[j * 36 + 31] = 0.f;
    }
    for (int i = tid; i < 264; i += 256) Kt[30 * 132 + i] = 0.f;
    __syncthreads();

    int warpM = warp & 3, warpN = warp >> 2;
    float acc[2][8][4] = {};
#pragma unroll
    for (int kk = 0; kk < 32; kk += 8) {
        unsigned afr[2][4], bfr[8][2];
#pragma unroll
        for (int mi = 0; mi < 2; mi++) {
            const float* pa = Qs + (warpM * 32 + mi * 16 + g) * 36 + kk + t;
            afr[mi][0] = __float_as_uint(pa[0]);
            afr[mi][1] = __float_as_uint(pa[8 * 36]);
            afr[mi][2] = __float_as_uint(pa[4]);
            afr[mi][3] = __float_as_uint(pa[8 * 36 + 4]);
        }
#pragma unroll
        for (int ni = 0; ni < 8; ni++) {
            const float* pbp = Kt + (kk + t) * 132 + warpN * 64 + ni * 8 + g;
            bfr[ni][0] = __float_as_uint(pbp[0]);
            bfr[ni][1] = __float_as_uint(pbp[4 * 132]);
        }
#pragma unroll
        for (int mi = 0; mi < 2; mi++)
#pragma unroll
            for (int ni = 0; ni < 8; ni++)
                mma_tf32(acc[mi][ni], afr[mi][0], afr[mi][1], afr[mi][2], afr[mi][3],
                         bfr[ni][0], bfr[ni][1]);
    }
    __syncthreads();

    const float* mwin = mask + (size_t)win * (Nn * Nn);
    const float* bch  = bc + (size_t)h * (Nn * Nn);
#pragma unroll
    for (int mi = 0; mi < 2; mi++) {
#pragma unroll
        for (int hf = 0; hf < 2; hf++) {
            int r = warpM * 32 + mi * 16 + hf * 8 + g;
            float s = 0.f;
#pragma unroll
            for (int ni = 0; ni < 8; ni++) {
                int c0 = warpN * 64 + ni * 8 + 2 * t;
                float2 b2 = *(const float2*)(bch + r * 128 + c0);
                float2 m2 = *(const float2*)(mwin + r * 128 + c0);
                float p0 = __expf(fminf(acc[mi][ni][hf * 2 + 0] + b2.x + m2.x, 60.f));
                float p1 = __expf(fminf(acc[mi][ni][hf * 2 + 1] + b2.y + m2.y, 60.f));
                s += p0 + p1;
                *(float2*)(Ps + r * 132 + c0) = make_float2(p0, p1);
            }
            s += __shfl_xor_sync(0xffffffffu, s, 1);
            s += __shfl_xor_sync(0xffffffffu, s, 2);
            if (t == 0) rsum2[r * 2 + warpN] = s;
        }
    }
    __syncthreads();
    for (int r = tid; r < 128; r += 256) rinv[r] = 1.f / (rsum2[2 * r] + rsum2[2 * r + 1]);
    __syncthreads();

    float oacc[4][4] = {};
    int rb = warp * 16;
#pragma unroll
    for (int kk = 0; kk < 128; kk += 8) {
        const float* pa = Ps + (rb + g) * 132 + kk + t;
        unsigned a0 = __float_as_uint(pa[0]);
        unsigned a1 = __float_as_uint(pa[8 * 132]);
        unsigned a2 = __float_as_uint(pa[4]);
        unsigned a3 = __float_as_uint(pa[8 * 132 + 4]);
        unsigned bfr[4][2];
#pragma unroll
        for (int ni = 0; ni < 4; ni++) {
            const float* pbp = Vs + (kk + t) * 36 + ni * 8 + g;
            bfr[ni][0] = __float_as_uint(pbp[0]);
            bfr[ni][1] = __float_as_uint(pbp[4 * 36]);
        }
#pragma unroll
        for (int ni = 0; ni < 4; ni++)
            mma_tf32(oacc[ni], a0, a1, a2, a3, bfr[ni][0], bfr[ni][1]);
    }
#pragma unroll
    for (int hf = 0; hf < 2; hf++) {
        int r = rb + hf * 8 + g;
        float inv = rinv[r];
        __half* orow = xo + (size_t)(win * Nn + r) * KP2 + Cc + h * HDd;
#pragma unroll
        for (int ni = 0; ni < 4; ni++) {
            int d0 = ni * 8 + 2 * t;
            if (d0 < 30)
                *(__half2*)(orow + d0) = __floats2half2_rn(oacc[ni][hf * 2 + 0] * inv,
                                                           oacc[ni][hf * 2 + 1] * inv);
        }
    }
}

// ---------------- mutual attention via tf32 mma (64x64) ----------------
__global__ __launch_bounds__(128)
void attn_mut_mma_k(const float* __restrict__ qkv,
                    const float* __restrict__ mask,
                    __half* __restrict__ xo)
{
    __shared__ float Qs[64 * 36];
    __shared__ float Kt[32 * 68];
    __shared__ float Vs[64 * 36];
    __shared__ float Ps[64 * 68];
    __shared__ float rinv[64];

    int h    = blockIdx.x;
    int win  = blockIdx.y;
    int part = blockIdx.z;
    int tid = threadIdx.x, lane = tid & 31, warp = tid >> 5;
    int g = lane >> 2, t = lane & 3;
    int kvoff = (part == 0) ? 0 : 64;
    int qoff  = (part == 0) ? 64 : 0;
    const float* base = qkv + (size_t)win * Nn * (3 * Cc);

    for (int i2 = tid; i2 < 64 * 15; i2 += 128) {
        int j = i2 / 15, d2 = i2 - j * 15;
        const float* qrow = base + (qoff + j)  * (3 * Cc) + h * HDd + 2 * d2;
        const float* krow = base + (kvoff + j) * (3 * Cc) + h * HDd + 2 * d2;
        float2 q = *(const float2*)(qrow);
        float2 k = *(const float2*)(krow + Cc);
        float2 v = *(const float2*)(krow + 2 * Cc);
        Qs[j * 36 + 2 * d2]     = q.x * SCALEF;
        Qs[j * 36 + 2 * d2 + 1] = q.y * SCALEF;
        Kt[(2 * d2) * 68 + j]     = k.x;
        Kt[(2 * d2 + 1) * 68 + j] = k.y;
        Vs[j * 36 + 2 * d2]     = v.x;
        Vs[j * 36 + 2 * d2 + 1] = v.y;
    }
    for (int j = tid; j < 64; j += 128) {
        Qs[j * 36 + 30] = 0.f; Qs[j * 36 + 31] = 0.f;
        Vs[j * 36 + 30] = 0.f; Vs[j * 36 + 31] = 0.f;
    }
    for (int i = tid; i < 136; i += 128) Kt[30 * 68 + i] = 0.f;
    __syncthreads();

    int rb = warp * 16;
    float acc[8][4] = {};
#pragma unroll
    for (int kk = 0; kk < 32; kk += 8) {
        const float* pa = Qs + (rb + g) * 36 + kk + t;
        unsigned a0 = __float_as_uint(pa[0]);
        unsigned a1 = __float_as_uint(pa[8 * 36]);
        unsigned a2 = __float_as_uint(pa[4]);
        unsigned a3 = __float_as_uint(pa[8 * 36 + 4]);
        unsigned bfr[8][2];
#pragma unroll
        for (int ni = 0; ni < 8; ni++) {
            const float* pbp = Kt + (kk + t) * 68 + ni * 8 + g;
            bfr[ni][0] = __float_as_uint(pbp[0]);
            bfr[ni][1] = __float_as_uint(pbp[4 * 68]);
        }
#pragma unroll
        for (int ni = 0; ni < 8; ni++)
            mma_tf32(acc[ni], a0, a1, a2, a3, bfr[ni][0], bfr[ni][1]);
    }

    const float* mwin = mask + (size_t)win * (Nn * Nn);
#pragma unroll
    for (int hf = 0; hf < 2; hf++) {
        int r = rb + hf * 8 + g;
        float s = 0.f;
#pragma unroll
        for (int ni = 0; ni < 8; ni++) {
            int c0 = ni * 8 + 2 * t;
            float2 m2 = *(const float2*)(mwin + r * 128 + c0);
            float p0 = __expf(fminf(acc[ni][hf * 2 + 0] + m2.x, 60.f));
            float p1 = __expf(fminf(acc[ni][hf * 2 + 1] + m2.y, 60.f));
            s += p0 + p1;
            *(float2*)(Ps + r * 68 + c0) = make_float2(p0, p1);
        }
        s += __shfl_xor_sync(0xffffffffu, s, 1);
        s += __shfl_xor_sync(0xffffffffu, s, 2);
        if (t == 0) rinv[r] = 1.f / s;
    }
    __syncthreads();

    float oacc[4][4] = {};
#pragma unroll
    for (int kk = 0; kk < 64; kk += 8) {
        const float* pa = Ps + (rb + g) * 68 + kk + t;
        unsigned a0 = __float_as_uint(pa[0]);
        unsigned a1 = __float_as_uint(pa[8 * 68]);
        unsigned a2 = __float_as_uint(pa[4]);
        unsigned a3 = __float_as_uint(pa[8 * 68 + 4]);
        unsigned bfr[4][2];
#pragma unroll
        for (int ni = 0; ni < 4; ni++) {
            const float* pbp = Vs + (kk + t) * 36 + ni * 8 + g;
            bfr[ni][0] = __float_as_uint(pbp[0]);
            bfr[ni][1] = __float_as_uint(pbp[4 * 36]);
        }
#pragma unroll
        for (int ni = 0; ni < 4; ni++)
            mma_tf32(oacc[ni], a0, a1, a2, a3, bfr[ni][0], bfr[ni][1]);
    }
#pragma unroll
    for (int hf = 0; hf < 2; hf++) {
        int r = rb + hf * 8 + g;
        float inv = rinv[r];
        __half* orow = xo + (size_t)(win * Nn + part * 64 + r) * KP2 + h * HDd;
#pragma unroll
        for (int ni = 0; ni < 4; ni++) {
            int d0 = ni * 8 + 2 * t;
            if (d0 < 30)
                *(__half2*)(orow + d0) = __floats2half2_rn(oacc[ni][hf * 2 + 0] * inv,
                                                           oacc[ni][hf * 2 + 1] * inv);
        }
    }
}

// ---------------- launch ----------------
extern "C" void kernel_launch(void* const* d_in, const int* in_sizes, int n_in,
                              void* d_out, int out_size)
{
    const float* x        = (const float*)d_in[0];
    const float* mask     = (const float*)d_in[1];
    const float* g1       = (const float*)d_in[2];
    const float* b1       = (const float*)d_in[3];
    const float* g2       = (const float*)d_in[4];
    const float* b2       = (const float*)d_in[5];
    const float* w_qkv_s  = (const float*)d_in[6];
    const float* b_qkv_s  = (const float*)d_in[7];
    const float* w_qkv_m  = (const float*)d_in[8];
    const float* b_qkv_m  = (const float*)d_in[9];
    const float* rpb      = (const float*)d_in[10];
    const float* pos_bias = (const float*)d_in[11];
    const float* w_proj   = (const float*)d_in[12];
    const float* b_proj   = (const float*)d_in[13];
    const float* w_fc11   = (const float*)d_in[14];
    const float* b_fc11   = (const float*)d_in[15];
    const float* w_fc12   = (const float*)d_in[16];
    const float* b_fc12   = (const float*)d_in[17];
    const float* w_fc2    = (const float*)d_in[18];
    const float* b_fc2    = (const float*)d_in[19];
    const int*   rpi      = (const int*)d_in[20];
    float* out = (float*)d_out;

    __half *p_xw_h, *p_xwp_h, *p_xo_h, *p_h2_h, *p_hid_h;
    __half *p_wqs, *p_wqm, *p_wpj, *p_w11, *p_w12, *p_wf2;
    float *p_qkvs, *p_qkvm, *p_y, *p_a1, *p_bc;
    cudaGetSymbolAddress((void**)&p_xw_h,  g_xw_h);
    cudaGetSymbolAddress((void**)&p_xwp_h, g_xwp_h);
    cudaGetSymbolAddress((void**)&p_qkvs,  g_qkvs);
    cudaGetSymbolAddress((void**)&p_qkvm,  g_qkvm);
    cudaGetSymbolAddress((void**)&p_xo_h,  g_xo_h);
    cudaGetSymbolAddress((void**)&p_y,     g_y);
    cudaGetSymbolAddress((void**)&p_h2_h,  g_h2_h);
    cudaGetSymbolAddress((void**)&p_a1,    g_a1);
    cudaGetSymbolAddress((void**)&p_hid_h, g_hid_h);
    cudaGetSymbolAddress((void**)&p_bc,    g_bc);
    cudaGetSymbolAddress((void**)&p_wqs,   g_wqkvs_t);
    cudaGetSymbolAddress((void**)&p_wqm,   g_wqkvm_t);
    cudaGetSymbolAddress((void**)&p_wpj,   g_wproj_t);
    cudaGetSymbolAddress((void**)&p_w11,   g_wfc11_t);
    cudaGetSymbolAddress((void**)&p_w12,   g_wfc12_t);
    cudaGetSymbolAddress((void**)&p_wf2,   g_wfc2_t);

    const int M = NTOK;
    auto ggrid = [](int N) { return dim3((unsigned)((N + 127) / 128), NTOK / 128); };

    static int attrSet = 0;
    if (!attrSet) {
        cudaFuncSetAttribute(attn_self_mma_k,
                             cudaFuncAttributeMaxDynamicSharedMemorySize,
                             SELF_SMEM_FLOATS * 4);
        cudaFuncSetAttribute(gemm_h_k,
                             cudaFuncAttributeMaxDynamicSharedMemorySize,
                             GEMM_SMEM_BYTES);
        attrSet = 1;
    }

    // weight conversion + transposition (half, [N][Kp])
    wconv_k<<<(540 * KP1 + 255) / 256, 256>>>(w_qkv_s, p_wqs, Cc,   3 * Cc, KP1);
    wconv_k<<<(540 * KP1 + 255) / 256, 256>>>(w_qkv_m, p_wqm, Cc,   3 * Cc, KP1);
    wconv_k<<<(180 * KP2 + 255) / 256, 256>>>(w_proj,  p_wpj, 2 * Cc, Cc,   KP2);
    wconv_k<<<(360 * KP1 + 255) / 256, 256>>>(w_fc11,  p_w11, Cc,   HIDd,  KP1);
    wconv_k<<<(360 * KP1 + 255) / 256, 256>>>(w_fc12,  p_w12, Cc,   HIDd,  KP1);
    wconv_k<<<(180 * KP2 + 255) / 256, 256>>>(w_fc2,   p_wf2, HIDd, Cc,    KP2);
    pad_k<<<(NTOK * 84 + 255) / 256, 256>>>();
    bias_comb_k<<<(NHh * Nn * Nn + 255) / 256, 256>>>(rpb, rpi, p_bc);

    ln1_window_k<<<(NTOK * 32 + 255) / 256, 256>>>(x, g1, b1, pos_bias, p_xw_h, p_xwp_h);

    gemm_h_k<<<ggrid(3 * Cc), 256, GEMM_SMEM_BYTES>>>(
        p_xw_h, p_wqs, b_qkv_s, nullptr, p_qkvs, M, 3 * Cc, KP1, 3 * Cc, 0);
    gemm_h_k<<<ggrid(3 * Cc), 256, GEMM_SMEM_BYTES>>>(
        p_xwp_h, p_wqm, b_qkv_m, nullptr, p_qkvm, M, 3 * Cc, KP1, 3 * Cc, 0);

    attn_self_mma_k<<<dim3(NHh, NWIN), 256, SELF_SMEM_FLOATS * 4>>>(
        p_qkvs, mask, p_bc, p_xo_h);
    attn_mut_mma_k<<<dim3(NHh, NWIN, 2), 128>>>(p_qkvm, mask, p_xo_h);

    gemm_h_k<<<ggrid(Cc), 256, GEMM_SMEM_BYTES>>>(
        p_xo_h, p_wpj, b_proj, x, p_y, M, Cc, KP2, Cc, 1);
    ln2_k<<<(NTOK * 32 + 255) / 256, 256>>>(p_y, g2, b2, p_h2_h);
    gemm_h_k<<<ggrid(HIDd), 256, GEMM_SMEM_BYTES>>>(
        p_h2_h, p_w11, b_fc11, nullptr, p_a1, M, HIDd, KP1, HIDd, 0);
    gemm_h_k<<<ggrid(HIDd), 256, GEMM_SMEM_BYTES>>>(
        p_h2_h, p_w12, b_fc12, p_a1, p_hid_h, M, HIDd, KP1, KP2, 2);
    gemm_h_k<<<ggrid(Cc), 256, GEMM_SMEM_BYTES>>>(
        p_hid_h, p_wf2, b_fc2, p_y, out, M, Cc, KP2, Cc, 3);

    (void)in_sizes; (void)n_in; (void)out_size;
}